// round 14
// baseline (speedup 1.0000x reference)
#include <cuda_runtime.h>
#include <cuda_bf16.h>
#include <math.h>
#include <stdint.h>

// ---------------- problem constants ----------------
#define BB 16
#define HH 64
#define WW 64
#define CC 192
#define HD 32
#define NH 6
#define SH 4
#define NW 64
#define TOK (BB*HH*WW)        // 65536
#define PPW 64

// ---------------- scratch (device globals) ----------------
__device__ __nv_bfloat16 g_hwin_bf[TOK * CC];
__device__ __nv_bfloat16 g_qkv_bf [TOK * 3 * CC];
__device__ __nv_bfloat16 g_attn_bf[TOK * CC];
__device__ float         g_x1     [TOK * CC];
__device__ __nv_bfloat16 g_h2_bf  [TOK * CC];
__device__ __nv_bfloat16 g_hid_bf [TOK * 4 * CC];
__device__ __nv_bfloat16 g_wqkvT [576 * 192];
__device__ __nv_bfloat16 g_wprojT[192 * 192];
__device__ __nv_bfloat16 g_wmlp1T[768 * 192];
__device__ __nv_bfloat16 g_wmlp2T[192 * 768];

// ---------------- PTX helpers ----------------
__device__ __forceinline__ uint32_t smem_u32(const void* p) {
    uint32_t a;
    asm("{ .reg .u64 t; cvta.to.shared.u64 t, %1; cvt.u32.u64 %0, t; }" : "=r"(a) : "l"(p));
    return a;
}
__device__ __forceinline__ void ldsm_x4(uint32_t* r, uint32_t addr) {
    asm volatile("ldmatrix.sync.aligned.m8n8.x4.shared.b16 {%0,%1,%2,%3}, [%4];"
        : "=r"(r[0]), "=r"(r[1]), "=r"(r[2]), "=r"(r[3]) : "r"(addr));
}
__device__ __forceinline__ void ldsm_x2(uint32_t* r, uint32_t addr) {
    asm volatile("ldmatrix.sync.aligned.m8n8.x2.shared.b16 {%0,%1}, [%2];"
        : "=r"(r[0]), "=r"(r[1]) : "r"(addr));
}
__device__ __forceinline__ void ldsm_x4t(uint32_t* r, uint32_t addr) {
    asm volatile("ldmatrix.sync.aligned.m8n8.x4.trans.shared.b16 {%0,%1,%2,%3}, [%4];"
        : "=r"(r[0]), "=r"(r[1]), "=r"(r[2]), "=r"(r[3]) : "r"(addr));
}
__device__ __forceinline__ void mma16816(float* c, const uint32_t* a, const uint32_t* b) {
    asm volatile(
        "mma.sync.aligned.m16n8k16.row.col.f32.bf16.bf16.f32 "
        "{%0,%1,%2,%3}, {%4,%5,%6,%7}, {%8,%9}, {%0,%1,%2,%3};"
        : "+f"(c[0]), "+f"(c[1]), "+f"(c[2]), "+f"(c[3])
        : "r"(a[0]), "r"(a[1]), "r"(a[2]), "r"(a[3]), "r"(b[0]), "r"(b[1]));
}
__device__ __forceinline__ uint32_t packbf(float a, float b) {
    __nv_bfloat162 t = __floats2bfloat162_rn(a, b);
    return *(uint32_t*)&t;
}
#define CP16(dst, src) \
    asm volatile("cp.async.cg.shared.global [%0], [%1], 16;" :: "r"(dst), "l"(src))
#define CPCOMMIT() asm volatile("cp.async.commit_group;" ::)
#define CPWAIT1()  asm volatile("cp.async.wait_group 1;" ::)
#define CPWAIT0()  asm volatile("cp.async.wait_group 0;" ::)

// ---------------- coalesced tiled transpose + bf16 convert (all 4 weights) ----------------
__global__ __launch_bounds__(256)
void wconv_all(const float* __restrict__ w0, __nv_bfloat16* __restrict__ t0,
               const float* __restrict__ w1, __nv_bfloat16* __restrict__ t1,
               const float* __restrict__ w2, __nv_bfloat16* __restrict__ t2,
               const float* __restrict__ w3, __nv_bfloat16* __restrict__ t3) {
    __shared__ float tile[32][33];
    int bid = blockIdx.x;
    const float* w; __nv_bfloat16* t; int K, N, base;
    if      (bid < 108) { w = w0; t = t0; K = 192; N = 576; base = bid; }
    else if (bid < 144) { w = w1; t = t1; K = 192; N = 192; base = bid - 108; }
    else if (bid < 288) { w = w2; t = t2; K = 192; N = 768; base = bid - 144; }
    else                { w = w3; t = t3; K = 768; N = 192; base = bid - 288; }
    int ntiles_n = N >> 5;
    int tk = (base / ntiles_n) << 5;
    int tn = (base % ntiles_n) << 5;
    int tx = threadIdx.x & 31, ty = threadIdx.x >> 5;

    #pragma unroll
    for (int r = 0; r < 4; r++) {
        int k = tk + ty + r * 8;
        tile[ty + r * 8][tx] = w[(size_t)k * N + tn + tx];
    }
    __syncthreads();
    #pragma unroll
    for (int r = 0; r < 4; r++) {
        int n = tn + ty + r * 8;
        t[(size_t)n * K + tk + tx] = __float2bfloat16(tile[tx][ty + r * 8]);
    }
}

// ---------------- LN1 + roll(-4,-4) + window partition -> bf16 (half-warp/token, float4) ----------------
__global__ __launch_bounds__(256)
void ln1_window_kernel(const float* __restrict__ x,
                       const float* __restrict__ g,
                       const float* __restrict__ b) {
    int tid = threadIdx.x;
    int token = blockIdx.x * 16 + (tid >> 4);
    int l = tid & 15;
    int b_  = token >> 12;
    int rem = token & 4095;
    int wn  = rem >> 6;
    int t   = rem & 63;
    int y  = (((wn >> 3) << 3) + (t >> 3) + SH) & (HH - 1);
    int xx = (((wn & 7)  << 3) + (t & 7)  + SH) & (WW - 1);
    const float4* src = (const float4*)(x + (((size_t)b_ * HH + y) * WW + xx) * CC);

    float4 v[3];
    float s = 0.f;
    #pragma unroll
    for (int i = 0; i < 3; i++) {
        v[i] = src[l + 16 * i];
        s += v[i].x + v[i].y + v[i].z + v[i].w;
    }
    #pragma unroll
    for (int o = 8; o; o >>= 1) s += __shfl_xor_sync(0xffffffffu, s, o);
    float mu = s * (1.f / CC);
    float s2 = 0.f;
    #pragma unroll
    for (int i = 0; i < 3; i++) {
        float d0 = v[i].x - mu, d1 = v[i].y - mu, d2 = v[i].z - mu, d3 = v[i].w - mu;
        s2 += d0 * d0 + d1 * d1 + d2 * d2 + d3 * d3;
    }
    #pragma unroll
    for (int o = 8; o; o >>= 1) s2 += __shfl_xor_sync(0xffffffffu, s2, o);
    float inv = rsqrtf(s2 * (1.f / CC) + 1e-5f);

    uint2* dst = (uint2*)(g_hwin_bf + (size_t)token * CC);
    const float4* gp = (const float4*)g;
    const float4* bp = (const float4*)b;
    #pragma unroll
    for (int i = 0; i < 3; i++) {
        float4 gg = gp[l + 16 * i];
        float4 bb = bp[l + 16 * i];
        float h0 = (v[i].x - mu) * inv * gg.x + bb.x;
        float h1 = (v[i].y - mu) * inv * gg.y + bb.y;
        float h2 = (v[i].z - mu) * inv * gg.z + bb.z;
        float h3 = (v[i].w - mu) * inv * gg.w + bb.w;
        uint2 o2;
        o2.x = packbf(h0, h1);
        o2.y = packbf(h2, h3);
        dst[l + 16 * i] = o2;
    }
}

// ---------------- HMMA attention: 1 block = (window, 2 heads), 4 warps ----------------
#define AT_SMEM (30720 + 1808)
__global__ __launch_bounds__(128)
void attn_mma_kernel(const float* __restrict__ rel_pos) {
    extern __shared__ char sm[];
    __nv_bfloat16* base = (__nv_bfloat16*)sm;   // 6 x [64][40]: q0,q1,k0,k1,v0,v1
    float*         rs   = (float*)(sm + 30720); // [2][225]

    int tid = threadIdx.x;
    int win = blockIdx.x;
    int h0  = blockIdx.y * 2;
    int wn  = win & 63;
    int tokbase = win * 64;
    bool lastRow = (wn >> 3) == 7;
    bool lastCol = (wn & 7) == 7;

    {
        const uint4* src = (const uint4*)(g_qkv_bf + (size_t)tokbase * 576);
        #pragma unroll
        for (int i = 0; i < 12; i++) {
            int e = tid + 128 * i;           // 0..1535
            int mat = e >> 9;                // 0=q 1=k 2=v
            int rem = e & 511;
            int r = rem >> 3;
            int lh = (rem >> 2) & 1;
            int c4 = rem & 3;
            uint4 v = src[r * 72 + mat * 24 + (h0 + lh) * 4 + c4];
            *(uint4*)(base + (mat * 2 + lh) * 2560 + r * 40 + c4 * 8) = v;
        }
        for (int i = tid; i < 450; i += 128) rs[i] = rel_pos[h0 * 225 + i];
    }
    __syncthreads();

    int wid = tid >> 5, lane = tid & 31;
    int lh = wid >> 1;
    int mhalf = wid & 1;
    uint32_t qb = smem_u32(base + lh * 2560);
    uint32_t kb = smem_u32(base + (2 + lh) * 2560);
    uint32_t vb = smem_u32(base + (4 + lh) * 2560);

    float sacc[2][8][4];
    #pragma unroll
    for (int mt = 0; mt < 2; mt++)
        #pragma unroll
        for (int nt = 0; nt < 8; nt++)
            #pragma unroll
            for (int e = 0; e < 4; e++) sacc[mt][nt][e] = 0.f;

    #pragma unroll
    for (int ks16 = 0; ks16 < 2; ks16++) {
        uint32_t a[2][4];
        #pragma unroll
        for (int mt = 0; mt < 2; mt++) {
            int row = mhalf * 32 + mt * 16 + (lane & 15);
            ldsm_x4(a[mt], qb + (row * 40 + ks16 * 16 + (lane >> 4) * 8) * 2);
        }
        uint32_t bf[8][2];
        #pragma unroll
        for (int ntp = 0; ntp < 4; ntp++) {
            uint32_t t4[4];
            ldsm_x4(t4, kb + ((ntp * 16 + (lane & 7) + ((lane >> 4) & 1) * 8) * 40
                              + ks16 * 16 + ((lane >> 3) & 1) * 8) * 2);
            bf[2 * ntp][0] = t4[0]; bf[2 * ntp][1] = t4[1];
            bf[2 * ntp + 1][0] = t4[2]; bf[2 * ntp + 1][1] = t4[3];
        }
        #pragma unroll
        for (int mt = 0; mt < 2; mt++)
            #pragma unroll
            for (int nt = 0; nt < 8; nt++)
                mma16816(sacc[mt][nt], a[mt], bf[nt]);
    }

    const float* rph = rs + lh * 225;
    #pragma unroll
    for (int mt = 0; mt < 2; mt++) {
        #pragma unroll
        for (int half = 0; half < 2; half++) {
            int p = mhalf * 32 + mt * 16 + (lane >> 2) + half * 8;
            int pi = p >> 3, pj = p & 7;
            float mx = -INFINITY;
            #pragma unroll
            for (int nt = 0; nt < 8; nt++) {
                #pragma unroll
                for (int e = 0; e < 2; e++) {
                    int qt = nt * 8 + (lane & 3) * 2 + e;
                    int qi = qt >> 3, qj = qt & 7;
                    float s = sacc[mt][nt][half * 2 + e] * 0.17677669529663687f
                            + rph[(pi - qi + 7) * 15 + (pj - qj + 7)];
                    bool msk = (lastRow && ((pi < SH) != (qi < SH))) ||
                               (lastCol && ((pj < SH) != (qj < SH)));
                    s = msk ? -INFINITY : s;
                    sacc[mt][nt][half * 2 + e] = s;
                    mx = fmaxf(mx, s);
                }
            }
            mx = fmaxf(mx, __shfl_xor_sync(0xffffffffu, mx, 1));
            mx = fmaxf(mx, __shfl_xor_sync(0xffffffffu, mx, 2));
            float sum = 0.f;
            #pragma unroll
            for (int nt = 0; nt < 8; nt++) {
                #pragma unroll
                for (int e = 0; e < 2; e++) {
                    float ex = __expf(sacc[mt][nt][half * 2 + e] - mx);
                    sacc[mt][nt][half * 2 + e] = ex;
                    sum += ex;
                }
            }
            sum += __shfl_xor_sync(0xffffffffu, sum, 1);
            sum += __shfl_xor_sync(0xffffffffu, sum, 2);
            float inv = 1.f / sum;
            #pragma unroll
            for (int nt = 0; nt < 8; nt++) {
                #pragma unroll
                for (int e = 0; e < 2; e++)
                    sacc[mt][nt][half * 2 + e] *= inv;
            }
        }
    }

    float o[2][4][4];
    #pragma unroll
    for (int mt = 0; mt < 2; mt++)
        #pragma unroll
        for (int nt = 0; nt < 4; nt++)
            #pragma unroll
            for (int e = 0; e < 4; e++) o[mt][nt][e] = 0.f;

    #pragma unroll
    for (int j = 0; j < 4; j++) {
        uint32_t bf[4][2];
        #pragma unroll
        for (int ntp = 0; ntp < 2; ntp++) {
            uint32_t t4[4];
            ldsm_x4t(t4, vb + ((j * 16 + (lane & 7) + ((lane >> 3) & 1) * 8) * 40
                               + ntp * 16 + ((lane >> 4) & 1) * 8) * 2);
            bf[2 * ntp][0] = t4[0]; bf[2 * ntp][1] = t4[1];
            bf[2 * ntp + 1][0] = t4[2]; bf[2 * ntp + 1][1] = t4[3];
        }
        #pragma unroll
        for (int mt = 0; mt < 2; mt++) {
            uint32_t afr[4];
            afr[0] = packbf(sacc[mt][2 * j    ][0], sacc[mt][2 * j    ][1]);
            afr[1] = packbf(sacc[mt][2 * j    ][2], sacc[mt][2 * j    ][3]);
            afr[2] = packbf(sacc[mt][2 * j + 1][0], sacc[mt][2 * j + 1][1]);
            afr[3] = packbf(sacc[mt][2 * j + 1][2], sacc[mt][2 * j + 1][3]);
            #pragma unroll
            for (int nt = 0; nt < 4; nt++)
                mma16816(o[mt][nt], afr, bf[nt]);
        }
    }

    #pragma unroll
    for (int mt = 0; mt < 2; mt++) {
        int prow = mhalf * 32 + mt * 16 + (lane >> 2);
        #pragma unroll
        for (int nt = 0; nt < 4; nt++) {
            int col = (h0 + lh) * 32 + nt * 8 + (lane & 3) * 2;
            __nv_bfloat16* dst = g_attn_bf + (size_t)(tokbase + prow) * CC + col;
            *(__nv_bfloat162*)dst = __floats2bfloat162_rn(o[mt][nt][0], o[mt][nt][1]);
            __nv_bfloat16* dst2 = dst + 8 * CC;
            *(__nv_bfloat162*)dst2 = __floats2bfloat162_rn(o[mt][nt][2], o[mt][nt][3]);
        }
    }
}

// ---------------- BIG GEMM (mlp2 shape): block 128(M) x 192(N), K in 64-chunks ----------------
// 8 warps, warp grid 2(M) x 4(N), warp tile 64 x 48. N-block = blockIdx.y.
// MODE 0: qkv  -> bf16 out (stride 576) + bias
// MODE 2: mlp1 -> gelu(acc+bias), bf16 out (stride 768)
// MODE 3: mlp2 -> fp32 out = res + acc + bias (stride 192)
#define BIG_SMEM (2*128*72*2 + 2*192*72*2)   // 92160
template <int MODE>
__global__ __launch_bounds__(256)
void gemm_big(const __nv_bfloat16* __restrict__ A,
              const __nv_bfloat16* __restrict__ BTfull,
              const float* __restrict__ biasFull,
              const float* __restrict__ res,
              void* __restrict__ outv,
              int K) {
    extern __shared__ char gsm[];
    uint32_t sA = smem_u32(gsm);          // [2][128][72]
    uint32_t sB = sA + 36864;             // [2][192][72]

    int tid  = threadIdx.x;
    int lane = tid & 31;
    int wid  = tid >> 5;
    int wm   = wid & 1;
    int wnw  = wid >> 1;
    int m0 = blockIdx.x * 128;
    int n0 = blockIdx.y * 192;
    const __nv_bfloat16* BT = BTfull + (size_t)n0 * K;
    const float* bias = biasFull + n0;
    const int nch = K >> 6;
    const int ostride = (MODE == 0) ? 576 : ((MODE == 2) ? 768 : 192);

    #pragma unroll
    for (int i = 0; i < 4; i++) {
        int e = tid + 256 * i; int r = e >> 3, c16 = e & 7;
        CP16(sA + (r * 72 + c16 * 8) * 2, A + (size_t)(m0 + r) * K + c16 * 8);
    }
    #pragma unroll
    for (int i = 0; i < 6; i++) {
        int e = tid + 256 * i; int r = e >> 3, c16 = e & 7;
        CP16(sB + (r * 72 + c16 * 8) * 2, BT + (size_t)r * K + c16 * 8);
    }
    CPCOMMIT();

    float acc[4][6][4];
    #pragma unroll
    for (int i = 0; i < 4; i++)
        #pragma unroll
        for (int j = 0; j < 6; j++)
            #pragma unroll
            for (int k = 0; k < 4; k++) acc[i][j][k] = 0.f;

    for (int c = 0; c < nch; c++) {
        int buf = c & 1;
        if (c + 1 < nch) {
            int kc = (c + 1) * 64;
            uint32_t dA = sA + (buf ^ 1) * 18432;
            uint32_t dB = sB + (buf ^ 1) * 27648;
            #pragma unroll
            for (int i = 0; i < 4; i++) {
                int e = tid + 256 * i; int r = e >> 3, c16 = e & 7;
                CP16(dA + (r * 72 + c16 * 8) * 2, A + (size_t)(m0 + r) * K + kc + c16 * 8);
            }
            #pragma unroll
            for (int i = 0; i < 6; i++) {
                int e = tid + 256 * i; int r = e >> 3, c16 = e & 7;
                CP16(dB + (r * 72 + c16 * 8) * 2, BT + (size_t)r * K + kc + c16 * 8);
            }
            CPCOMMIT();
            CPWAIT1();
        } else {
            CPWAIT0();
        }
        __syncthreads();

        uint32_t sAc = sA + buf * 18432;
        uint32_t sBc = sB + buf * 27648;
        #pragma unroll
        for (int ks = 0; ks < 4; ks++) {
            uint32_t a[4][4], b[6][2];
            #pragma unroll
            for (int mt = 0; mt < 4; mt++) {
                uint32_t addr = sAc + ((wm * 64 + mt * 16 + (lane & 15)) * 72
                                       + ks * 16 + (lane >> 4) * 8) * 2;
                ldsm_x4(a[mt], addr);
            }
            #pragma unroll
            for (int ntp = 0; ntp < 3; ntp++) {
                uint32_t t4[4];
                ldsm_x4(t4, sBc + ((wnw * 48 + ntp * 16 + (lane & 7) + ((lane >> 4) & 1) * 8) * 72
                                   + ks * 16 + ((lane >> 3) & 1) * 8) * 2);
                b[2 * ntp][0] = t4[0]; b[2 * ntp][1] = t4[1];
                b[2 * ntp + 1][0] = t4[2]; b[2 * ntp + 1][1] = t4[3];
            }
            #pragma unroll
            for (int mt = 0; mt < 4; mt++)
                #pragma unroll
                for (int nt = 0; nt < 6; nt++)
                    mma16816(acc[mt][nt], a[mt], b[nt]);
        }
        __syncthreads();
    }

    #pragma unroll
    for (int mt = 0; mt < 4; mt++) {
        #pragma unroll
        for (int half = 0; half < 2; half++) {
            int m = m0 + wm * 64 + mt * 16 + (lane >> 2) + half * 8;
            #pragma unroll
            for (int nt = 0; nt < 6; nt++) {
                int col = wnw * 48 + nt * 8 + (lane & 3) * 2;
                float v0 = acc[mt][nt][half * 2 + 0] + bias[col];
                float v1 = acc[mt][nt][half * 2 + 1] + bias[col + 1];
                if (MODE == 3) {
                    float* o = (float*)outv;
                    size_t i0 = (size_t)m * 192 + col;
                    o[i0]     = res[i0]     + v0;
                    o[i0 + 1] = res[i0 + 1] + v1;
                } else {
                    if (MODE == 2) {
                        v0 = 0.5f * v0 * (1.f + erff(v0 * 0.70710678118654752f));
                        v1 = 0.5f * v1 * (1.f + erff(v1 * 0.70710678118654752f));
                    }
                    __nv_bfloat16* o = (__nv_bfloat16*)outv + (size_t)m * ostride + n0 + col;
                    *(__nv_bfloat162*)o = __floats2bfloat162_rn(v0, v1);
                }
            }
        }
    }
}

// ---------------- proj GEMM (128x192) + un-window + residual + LN2, 512 threads ----------------
#define PROJ_SMEM (20480 + 76800 + 8192)   // 105472
__global__ __launch_bounds__(512)
void gemm_proj_ln(const __nv_bfloat16* __restrict__ A,
                  const __nv_bfloat16* __restrict__ BT,
                  const float* __restrict__ bias,
                  const float* __restrict__ res,
                  float* __restrict__ x1out,
                  const float* __restrict__ g2,
                  const float* __restrict__ b2,
                  __nv_bfloat16* __restrict__ h2out) {
    extern __shared__ char psm[];
    uint32_t sAbase = smem_u32(psm);              // [2][128][40] bf16
    uint32_t sBbase = sAbase + 20480;             // [192][200]   bf16
    float* part = (float*)(psm + 97280);          // [8][128][2]

    int tid  = threadIdx.x;
    int lane = tid & 31;
    int wid  = tid >> 5;
    int wm   = wid & 1;
    int wnw  = wid >> 1;
    int m0 = blockIdx.x * 128;
    const int K = 192;
    const int nch = 6;

    for (int i = tid; i < 192 * 24; i += 512) {
        int r = i / 24, c16 = i % 24;
        CP16(sBbase + (r * 200 + c16 * 8) * 2, BT + (size_t)r * 192 + c16 * 8);
    }
    {
        int r = tid >> 2, cs = (tid & 3) * 8;
        CP16(sAbase + (r * 40 + cs) * 2, A + (size_t)(m0 + r) * K + cs);
    }
    CPCOMMIT();

    float acc[4][3][4];
    #pragma unroll
    for (int i = 0; i < 4; i++)
        #pragma unroll
        for (int j = 0; j < 3; j++)
            #pragma unroll
            for (int k = 0; k < 4; k++) acc[i][j][k] = 0.f;

    for (int c = 0; c < nch; c++) {
        int buf = c & 1;
        if (c + 1 < nch) {
            int kc = (c + 1) * 32;
            int r = tid >> 2, cs = (tid & 3) * 8;
            CP16(sAbase + (buf ^ 1) * 10240 + (r * 40 + cs) * 2,
                 A + (size_t)(m0 + r) * K + kc + cs);
            CPCOMMIT();
            CPWAIT1();
        } else {
            CPWAIT0();
        }
        __syncthreads();

        uint32_t sA = sAbase + buf * 10240;
        #pragma unroll
        for (int ks = 0; ks < 2; ks++) {
            uint32_t a[4][4], b[3][2];
            #pragma unroll
            for (int mt = 0; mt < 4; mt++) {
                uint32_t addr = sA + ((wm * 64 + mt * 16 + (lane & 15)) * 40
                                      + ks * 16 + (lane >> 4) * 8) * 2;
                ldsm_x4(a[mt], addr);
            }
            {
                uint32_t t4[4];
                ldsm_x4(t4, sBbase + ((wnw * 24 + (lane & 7) + ((lane >> 4) & 1) * 8) * 200
                                      + c * 32 + ks * 16 + ((lane >> 3) & 1) * 8) * 2);
                b[0][0] = t4[0]; b[0][1] = t4[1];
                b[1][0] = t4[2]; b[1][1] = t4[3];
                int L = lane & 15;
                ldsm_x2(b[2], sBbase + ((wnw * 24 + 16 + (L & 7)) * 200
                                        + c * 32 + ks * 16 + (L >> 3) * 8) * 2);
            }
            #pragma unroll
            for (int mt = 0; mt < 4; mt++)
                #pragma unroll
                for (int nt = 0; nt < 3; nt++)
                    mma16816(acc[mt][nt], a[mt], b[nt]);
        }
        __syncthreads();
    }

    #pragma unroll
    for (int mt = 0; mt < 4; mt++) {
        #pragma unroll
        for (int half = 0; half < 2; half++) {
            int row = wm * 64 + mt * 16 + (lane >> 2) + half * 8;
            int m = m0 + row;
            int b_ = m >> 12, rem = m & 4095, wnn = rem >> 6, t = rem & 63;
            int y  = (((wnn >> 3) << 3) + (t >> 3) + SH) & 63;
            int xx = (((wnn & 7)  << 3) + (t & 7)  + SH) & 63;
            size_t pixbase = (size_t)(((b_ << 6) + y) * 64 + xx) * CC;
            float s = 0.f, s2 = 0.f;
            #pragma unroll
            for (int nt = 0; nt < 3; nt++) {
                #pragma unroll
                for (int e = 0; e < 2; e++) {
                    int col = wnw * 24 + nt * 8 + (lane & 3) * 2 + e;
                    float v = acc[mt][nt][half * 2 + e] + bias[col] + res[pixbase + col];
                    acc[mt][nt][half * 2 + e] = v;
                    x1out[pixbase + col] = v;
                    s += v; s2 += v * v;
                }
            }
            s  += __shfl_xor_sync(0xffffffffu, s, 1);
            s  += __shfl_xor_sync(0xffffffffu, s, 2);
            s2 += __shfl_xor_sync(0xffffffffu, s2, 1);
            s2 += __shfl_xor_sync(0xffffffffu, s2, 2);
            if ((lane & 3) == 0) {
                part[(wnw * 128 + row) * 2]     = s;
                part[(wnw * 128 + row) * 2 + 1] = s2;
            }
        }
    }
    __syncthreads();

    #pragma unroll
    for (int mt = 0; mt < 4; mt++) {
        #pragma unroll
        for (int half = 0; half < 2; half++) {
            int row = wm * 64 + mt * 16 + (lane >> 2) + half * 8;
            int m = m0 + row;
            int b_ = m >> 12, rem = m & 4095, wnn = rem >> 6, t = rem & 63;
            int y  = (((wnn >> 3) << 3) + (t >> 3) + SH) & 63;
            int xx = (((wnn & 7)  << 3) + (t & 7)  + SH) & 63;
            size_t pixbase = (size_t)(((b_ << 6) + y) * 64 + xx) * CC;
            float S = 0.f, S2 = 0.f;
            #pragma unroll
            for (int w = 0; w < 8; w++) {
                S  += part[(w * 128 + row) * 2];
                S2 += part[(w * 128 + row) * 2 + 1];
            }
            float mu  = S * (1.f / CC);
            float var = S2 * (1.f / CC) - mu * mu;
            float inv = rsqrtf(var + 1e-5f);
            #pragma unroll
            for (int nt = 0; nt < 3; nt++) {
                int col = wnw * 24 + nt * 8 + (lane & 3) * 2;
                float h0 = (acc[mt][nt][half * 2 + 0] - mu) * inv * g2[col]     + b2[col];
                float h1 = (acc[mt][nt][half * 2 + 1] - mu) * inv * g2[col + 1] + b2[col + 1];
                *(__nv_bfloat162*)(h2out + pixbase + col) = __floats2bfloat162_rn(h0, h1);
            }
        }
    }
}

// ---------------- launch ----------------
extern "C" void kernel_launch(void* const* d_in, const int* in_sizes, int n_in,
                              void* d_out, int out_size) {
    const float* x       = (const float*)d_in[0];
    const float* g1      = (const float*)d_in[1];
    const float* b1      = (const float*)d_in[2];
    const float* w_qkv   = (const float*)d_in[3];
    const float* b_qkv   = (const float*)d_in[4];
    const float* rel_pos = (const float*)d_in[5];
    const float* w_proj  = (const float*)d_in[6];
    const float* b_proj  = (const float*)d_in[7];
    const float* g2      = (const float*)d_in[8];
    const float* b2      = (const float*)d_in[9];
    const float* w_mlp1  = (const float*)d_in[10];
    const float* b_mlp1  = (const float*)d_in[11];
    const float* w_mlp2  = (const float*)d_in[12];
    const float* b_mlp2  = (const float*)d_in[13];
    float* out = (float*)d_out;

    __nv_bfloat16 *p_hwin, *p_qkv, *p_attn, *p_h2, *p_hid;
    __nv_bfloat16 *p_wqkvT, *p_wprojT, *p_wmlp1T, *p_wmlp2T;
    float *p_x1;
    cudaGetSymbolAddress((void**)&p_hwin,   g_hwin_bf);
    cudaGetSymbolAddress((void**)&p_qkv,    g_qkv_bf);
    cudaGetSymbolAddress((void**)&p_attn,   g_attn_bf);
    cudaGetSymbolAddress((void**)&p_x1,     g_x1);
    cudaGetSymbolAddress((void**)&p_h2,     g_h2_bf);
    cudaGetSymbolAddress((void**)&p_hid,    g_hid_bf);
    cudaGetSymbolAddress((void**)&p_wqkvT,  g_wqkvT);
    cudaGetSymbolAddress((void**)&p_wprojT, g_wprojT);
    cudaGetSymbolAddress((void**)&p_wmlp1T, g_wmlp1T);
    cudaGetSymbolAddress((void**)&p_wmlp2T, g_wmlp2T);

    cudaFuncSetAttribute(gemm_big<0>, cudaFuncAttributeMaxDynamicSharedMemorySize, BIG_SMEM);
    cudaFuncSetAttribute(gemm_big<2>, cudaFuncAttributeMaxDynamicSharedMemorySize, BIG_SMEM);
    cudaFuncSetAttribute(gemm_big<3>, cudaFuncAttributeMaxDynamicSharedMemorySize, BIG_SMEM);
    cudaFuncSetAttribute(gemm_proj_ln, cudaFuncAttributeMaxDynamicSharedMemorySize, PROJ_SMEM);
    cudaFuncSetAttribute(attn_mma_kernel, cudaFuncAttributeMaxDynamicSharedMemorySize, AT_SMEM);

    // weight transpose + convert (coalesced tiled, single launch)
    wconv_all<<<432, 256>>>(w_qkv, p_wqkvT, w_proj, p_wprojT,
                            w_mlp1, p_wmlp1T, w_mlp2, p_wmlp2T);

    // 1. LN1 + roll + window partition (bf16, half-warp/token float4)
    ln1_window_kernel<<<TOK / 16, 256>>>(x, g1, b1);

    // 2. qkv: [65536,192] @ [192,576] -> bf16 (big tile, 3 N-blocks)
    gemm_big<0><<<dim3(TOK / 128, 3), 256, BIG_SMEM>>>(p_hwin, p_wqkvT, b_qkv, nullptr, p_qkv, 192);

    // 3. windowed attention (HMMA, 128-thread blocks, 2 heads each)
    attn_mma_kernel<<<dim3(BB * NW, 3), 128, AT_SMEM>>>(rel_pos);

    // 4. proj + un-window + residual + LN2 (512 threads) -> g_x1 (fp32), g_h2 (bf16)
    gemm_proj_ln<<<TOK / 128, 512, PROJ_SMEM>>>(p_attn, p_wprojT, b_proj, x, p_x1, g2, b2, p_h2);

    // 5. mlp1 + gelu: [65536,192] @ [192,768] -> bf16 (big tile, 4 N-blocks)
    gemm_big<2><<<dim3(TOK / 128, 4), 256, BIG_SMEM>>>(p_h2, p_wmlp1T, b_mlp1, nullptr, p_hid, 192);

    // 6. mlp2 + residual: [65536,768] @ [768,192] -> fp32 out
    gemm_big<3><<<dim3(TOK / 128, 1), 256, BIG_SMEM>>>(p_hid, p_wmlp2T, b_mlp2, p_x1, out, 768);
}

// round 15
// speedup vs baseline: 1.0637x; 1.0637x over previous
#include <cuda_runtime.h>
#include <cuda_bf16.h>
#include <math.h>
#include <stdint.h>

// ---------------- problem constants ----------------
#define BB 16
#define HH 64
#define WW 64
#define CC 192
#define HD 32
#define NH 6
#define SH 4
#define NW 64
#define TOK (BB*HH*WW)        // 65536
#define PPW 64

// ---------------- scratch (device globals) ----------------
__device__ __nv_bfloat16 g_hwin_bf[TOK * CC];
__device__ __nv_bfloat16 g_qkv_bf [TOK * 3 * CC];
__device__ __nv_bfloat16 g_attn_bf[TOK * CC];
__device__ float         g_x1     [TOK * CC];
__device__ __nv_bfloat16 g_h2_bf  [TOK * CC];
__device__ __nv_bfloat16 g_hid_bf [TOK * 4 * CC];
__device__ __nv_bfloat16 g_wqkvT [576 * 192];
__device__ __nv_bfloat16 g_wprojT[192 * 192];
__device__ __nv_bfloat16 g_wmlp1T[768 * 192];
__device__ __nv_bfloat16 g_wmlp2T[192 * 768];

// ---------------- PTX helpers ----------------
__device__ __forceinline__ uint32_t smem_u32(const void* p) {
    uint32_t a;
    asm("{ .reg .u64 t; cvta.to.shared.u64 t, %1; cvt.u32.u64 %0, t; }" : "=r"(a) : "l"(p));
    return a;
}
__device__ __forceinline__ void ldsm_x4(uint32_t* r, uint32_t addr) {
    asm volatile("ldmatrix.sync.aligned.m8n8.x4.shared.b16 {%0,%1,%2,%3}, [%4];"
        : "=r"(r[0]), "=r"(r[1]), "=r"(r[2]), "=r"(r[3]) : "r"(addr));
}
__device__ __forceinline__ void ldsm_x2(uint32_t* r, uint32_t addr) {
    asm volatile("ldmatrix.sync.aligned.m8n8.x2.shared.b16 {%0,%1}, [%2];"
        : "=r"(r[0]), "=r"(r[1]) : "r"(addr));
}
__device__ __forceinline__ void ldsm_x4t(uint32_t* r, uint32_t addr) {
    asm volatile("ldmatrix.sync.aligned.m8n8.x4.trans.shared.b16 {%0,%1,%2,%3}, [%4];"
        : "=r"(r[0]), "=r"(r[1]), "=r"(r[2]), "=r"(r[3]) : "r"(addr));
}
__device__ __forceinline__ void mma16816(float* c, const uint32_t* a, const uint32_t* b) {
    asm volatile(
        "mma.sync.aligned.m16n8k16.row.col.f32.bf16.bf16.f32 "
        "{%0,%1,%2,%3}, {%4,%5,%6,%7}, {%8,%9}, {%0,%1,%2,%3};"
        : "+f"(c[0]), "+f"(c[1]), "+f"(c[2]), "+f"(c[3])
        : "r"(a[0]), "r"(a[1]), "r"(a[2]), "r"(a[3]), "r"(b[0]), "r"(b[1]));
}
__device__ __forceinline__ uint32_t packbf(float a, float b) {
    __nv_bfloat162 t = __floats2bfloat162_rn(a, b);
    return *(uint32_t*)&t;
}
#define CP16(dst, src) \
    asm volatile("cp.async.cg.shared.global [%0], [%1], 16;" :: "r"(dst), "l"(src))
#define CPCOMMIT() asm volatile("cp.async.commit_group;" ::)
#define CPWAIT1()  asm volatile("cp.async.wait_group 1;" ::)
#define CPWAIT0()  asm volatile("cp.async.wait_group 0;" ::)

// ---------------- coalesced tiled transpose + bf16 convert (all 4 weights) ----------------
__global__ __launch_bounds__(256)
void wconv_all(const float* __restrict__ w0, __nv_bfloat16* __restrict__ t0,
               const float* __restrict__ w1, __nv_bfloat16* __restrict__ t1,
               const float* __restrict__ w2, __nv_bfloat16* __restrict__ t2,
               const float* __restrict__ w3, __nv_bfloat16* __restrict__ t3) {
    __shared__ float tile[32][33];
    int bid = blockIdx.x;
    const float* w; __nv_bfloat16* t; int K, N, base;
    if      (bid < 108) { w = w0; t = t0; K = 192; N = 576; base = bid; }
    else if (bid < 144) { w = w1; t = t1; K = 192; N = 192; base = bid - 108; }
    else if (bid < 288) { w = w2; t = t2; K = 192; N = 768; base = bid - 144; }
    else                { w = w3; t = t3; K = 768; N = 192; base = bid - 288; }
    int ntiles_n = N >> 5;
    int tk = (base / ntiles_n) << 5;
    int tn = (base % ntiles_n) << 5;
    int tx = threadIdx.x & 31, ty = threadIdx.x >> 5;

    #pragma unroll
    for (int r = 0; r < 4; r++) {
        int k = tk + ty + r * 8;
        tile[ty + r * 8][tx] = w[(size_t)k * N + tn + tx];
    }
    __syncthreads();
    #pragma unroll
    for (int r = 0; r < 4; r++) {
        int n = tn + ty + r * 8;
        t[(size_t)n * K + tk + tx] = __float2bfloat16(tile[tx][ty + r * 8]);
    }
}

// ---------------- LN1 + roll(-4,-4) + window partition -> bf16 (half-warp/token, float4) ----------------
__global__ __launch_bounds__(256)
void ln1_window_kernel(const float* __restrict__ x,
                       const float* __restrict__ g,
                       const float* __restrict__ b) {
    int tid = threadIdx.x;
    int token = blockIdx.x * 16 + (tid >> 4);
    int l = tid & 15;
    int b_  = token >> 12;
    int rem = token & 4095;
    int wn  = rem >> 6;
    int t   = rem & 63;
    int y  = (((wn >> 3) << 3) + (t >> 3) + SH) & (HH - 1);
    int xx = (((wn & 7)  << 3) + (t & 7)  + SH) & (WW - 1);
    const float4* src = (const float4*)(x + (((size_t)b_ * HH + y) * WW + xx) * CC);

    float4 v[3];
    float s = 0.f;
    #pragma unroll
    for (int i = 0; i < 3; i++) {
        v[i] = src[l + 16 * i];
        s += v[i].x + v[i].y + v[i].z + v[i].w;
    }
    #pragma unroll
    for (int o = 8; o; o >>= 1) s += __shfl_xor_sync(0xffffffffu, s, o);
    float mu = s * (1.f / CC);
    float s2 = 0.f;
    #pragma unroll
    for (int i = 0; i < 3; i++) {
        float d0 = v[i].x - mu, d1 = v[i].y - mu, d2 = v[i].z - mu, d3 = v[i].w - mu;
        s2 += d0 * d0 + d1 * d1 + d2 * d2 + d3 * d3;
    }
    #pragma unroll
    for (int o = 8; o; o >>= 1) s2 += __shfl_xor_sync(0xffffffffu, s2, o);
    float inv = rsqrtf(s2 * (1.f / CC) + 1e-5f);

    uint2* dst = (uint2*)(g_hwin_bf + (size_t)token * CC);
    const float4* gp = (const float4*)g;
    const float4* bp = (const float4*)b;
    #pragma unroll
    for (int i = 0; i < 3; i++) {
        float4 gg = gp[l + 16 * i];
        float4 bb = bp[l + 16 * i];
        float h0 = (v[i].x - mu) * inv * gg.x + bb.x;
        float h1 = (v[i].y - mu) * inv * gg.y + bb.y;
        float h2 = (v[i].z - mu) * inv * gg.z + bb.z;
        float h3 = (v[i].w - mu) * inv * gg.w + bb.w;
        uint2 o2;
        o2.x = packbf(h0, h1);
        o2.y = packbf(h2, h3);
        dst[l + 16 * i] = o2;
    }
}

// ---------------- HMMA attention: 1 block = (window, 2 heads), 4 warps ----------------
#define AT_SMEM (30720 + 1808)
__global__ __launch_bounds__(128, 5)
void attn_mma_kernel(const float* __restrict__ rel_pos) {
    extern __shared__ char sm[];
    __nv_bfloat16* base = (__nv_bfloat16*)sm;   // 6 x [64][40]: q0,q1,k0,k1,v0,v1
    float*         rs   = (float*)(sm + 30720); // [2][225]

    int tid = threadIdx.x;
    int win = blockIdx.x;
    int h0  = blockIdx.y * 2;
    int wn  = win & 63;
    int tokbase = win * 64;
    bool lastRow = (wn >> 3) == 7;
    bool lastCol = (wn & 7) == 7;

    {
        const uint4* src = (const uint4*)(g_qkv_bf + (size_t)tokbase * 576);
        #pragma unroll
        for (int i = 0; i < 12; i++) {
            int e = tid + 128 * i;           // 0..1535
            int mat = e >> 9;                // 0=q 1=k 2=v
            int rem = e & 511;
            int r = rem >> 3;
            int lh = (rem >> 2) & 1;
            int c4 = rem & 3;
            uint4 v = src[r * 72 + mat * 24 + (h0 + lh) * 4 + c4];
            *(uint4*)(base + (mat * 2 + lh) * 2560 + r * 40 + c4 * 8) = v;
        }
        for (int i = tid; i < 450; i += 128) rs[i] = rel_pos[h0 * 225 + i];
    }
    __syncthreads();

    int wid = tid >> 5, lane = tid & 31;
    int lh = wid >> 1;
    int mhalf = wid & 1;
    uint32_t qb = smem_u32(base + lh * 2560);
    uint32_t kb = smem_u32(base + (2 + lh) * 2560);
    uint32_t vb = smem_u32(base + (4 + lh) * 2560);

    float sacc[2][8][4];
    #pragma unroll
    for (int mt = 0; mt < 2; mt++)
        #pragma unroll
        for (int nt = 0; nt < 8; nt++)
            #pragma unroll
            for (int e = 0; e < 4; e++) sacc[mt][nt][e] = 0.f;

    #pragma unroll
    for (int ks16 = 0; ks16 < 2; ks16++) {
        uint32_t a[2][4];
        #pragma unroll
        for (int mt = 0; mt < 2; mt++) {
            int row = mhalf * 32 + mt * 16 + (lane & 15);
            ldsm_x4(a[mt], qb + (row * 40 + ks16 * 16 + (lane >> 4) * 8) * 2);
        }
        uint32_t bf[8][2];
        #pragma unroll
        for (int ntp = 0; ntp < 4; ntp++) {
            uint32_t t4[4];
            ldsm_x4(t4, kb + ((ntp * 16 + (lane & 7) + ((lane >> 4) & 1) * 8) * 40
                              + ks16 * 16 + ((lane >> 3) & 1) * 8) * 2);
            bf[2 * ntp][0] = t4[0]; bf[2 * ntp][1] = t4[1];
            bf[2 * ntp + 1][0] = t4[2]; bf[2 * ntp + 1][1] = t4[3];
        }
        #pragma unroll
        for (int mt = 0; mt < 2; mt++)
            #pragma unroll
            for (int nt = 0; nt < 8; nt++)
                mma16816(sacc[mt][nt], a[mt], bf[nt]);
    }

    const float* rph = rs + lh * 225;
    #pragma unroll
    for (int mt = 0; mt < 2; mt++) {
        #pragma unroll
        for (int half = 0; half < 2; half++) {
            int p = mhalf * 32 + mt * 16 + (lane >> 2) + half * 8;
            int pi = p >> 3, pj = p & 7;
            float mx = -INFINITY;
            #pragma unroll
            for (int nt = 0; nt < 8; nt++) {
                #pragma unroll
                for (int e = 0; e < 2; e++) {
                    int qt = nt * 8 + (lane & 3) * 2 + e;
                    int qi = qt >> 3, qj = qt & 7;
                    float s = sacc[mt][nt][half * 2 + e] * 0.17677669529663687f
                            + rph[(pi - qi + 7) * 15 + (pj - qj + 7)];
                    bool msk = (lastRow && ((pi < SH) != (qi < SH))) ||
                               (lastCol && ((pj < SH) != (qj < SH)));
                    s = msk ? -INFINITY : s;
                    sacc[mt][nt][half * 2 + e] = s;
                    mx = fmaxf(mx, s);
                }
            }
            mx = fmaxf(mx, __shfl_xor_sync(0xffffffffu, mx, 1));
            mx = fmaxf(mx, __shfl_xor_sync(0xffffffffu, mx, 2));
            float sum = 0.f;
            #pragma unroll
            for (int nt = 0; nt < 8; nt++) {
                #pragma unroll
                for (int e = 0; e < 2; e++) {
                    float ex = __expf(sacc[mt][nt][half * 2 + e] - mx);
                    sacc[mt][nt][half * 2 + e] = ex;
                    sum += ex;
                }
            }
            sum += __shfl_xor_sync(0xffffffffu, sum, 1);
            sum += __shfl_xor_sync(0xffffffffu, sum, 2);
            float inv = 1.f / sum;
            #pragma unroll
            for (int nt = 0; nt < 8; nt++) {
                #pragma unroll
                for (int e = 0; e < 2; e++)
                    sacc[mt][nt][half * 2 + e] *= inv;
            }
        }
    }

    float o[2][4][4];
    #pragma unroll
    for (int mt = 0; mt < 2; mt++)
        #pragma unroll
        for (int nt = 0; nt < 4; nt++)
            #pragma unroll
            for (int e = 0; e < 4; e++) o[mt][nt][e] = 0.f;

    #pragma unroll
    for (int j = 0; j < 4; j++) {
        uint32_t bf[4][2];
        #pragma unroll
        for (int ntp = 0; ntp < 2; ntp++) {
            uint32_t t4[4];
            ldsm_x4t(t4, vb + ((j * 16 + (lane & 7) + ((lane >> 3) & 1) * 8) * 40
                               + ntp * 16 + ((lane >> 4) & 1) * 8) * 2);
            bf[2 * ntp][0] = t4[0]; bf[2 * ntp][1] = t4[1];
            bf[2 * ntp + 1][0] = t4[2]; bf[2 * ntp + 1][1] = t4[3];
        }
        #pragma unroll
        for (int mt = 0; mt < 2; mt++) {
            uint32_t afr[4];
            afr[0] = packbf(sacc[mt][2 * j    ][0], sacc[mt][2 * j    ][1]);
            afr[1] = packbf(sacc[mt][2 * j    ][2], sacc[mt][2 * j    ][3]);
            afr[2] = packbf(sacc[mt][2 * j + 1][0], sacc[mt][2 * j + 1][1]);
            afr[3] = packbf(sacc[mt][2 * j + 1][2], sacc[mt][2 * j + 1][3]);
            #pragma unroll
            for (int nt = 0; nt < 4; nt++)
                mma16816(o[mt][nt], afr, bf[nt]);
        }
    }

    #pragma unroll
    for (int mt = 0; mt < 2; mt++) {
        int prow = mhalf * 32 + mt * 16 + (lane >> 2);
        #pragma unroll
        for (int nt = 0; nt < 4; nt++) {
            int col = (h0 + lh) * 32 + nt * 8 + (lane & 3) * 2;
            __nv_bfloat16* dst = g_attn_bf + (size_t)(tokbase + prow) * CC + col;
            *(__nv_bfloat162*)dst = __floats2bfloat162_rn(o[mt][nt][0], o[mt][nt][1]);
            __nv_bfloat16* dst2 = dst + 8 * CC;
            *(__nv_bfloat162*)dst2 = __floats2bfloat162_rn(o[mt][nt][2], o[mt][nt][3]);
        }
    }
}

// ---------------- A-resident GEMM (K=192): block 128(M), N streamed in 64-chunks ----------------
#define ARES_SMEM (51200 + 2*25600)     // 102400
template <int MODE>
__global__ __launch_bounds__(256)
void gemm_ares(const __nv_bfloat16* __restrict__ A,
               const __nv_bfloat16* __restrict__ BT,
               const float* __restrict__ bias,
               __nv_bfloat16* __restrict__ outp,
               int N) {
    extern __shared__ char gsm[];
    uint32_t sA = smem_u32(gsm);          // [128][200] bf16
    uint32_t sB = sA + 51200;             // [2][64][200] bf16

    int tid  = threadIdx.x;
    int lane = tid & 31;
    int wid  = tid >> 5;
    int wm   = wid & 3;
    int wnw  = wid >> 2;
    int m0 = blockIdx.x * 128;
    const int K = 192;
    const int ostride = (MODE == 0) ? 576 : 768;

    #pragma unroll
    for (int i = 0; i < 12; i++) {
        int e = tid + 256 * i;
        int r = e / 24, c16 = e % 24;
        CP16(sA + (r * 200 + c16 * 8) * 2, A + (size_t)(m0 + r) * K + c16 * 8);
    }
    #pragma unroll
    for (int i = 0; i < 6; i++) {
        int e = tid + 256 * i;
        int r = e / 24, c16 = e % 24;
        CP16(sB + (r * 200 + c16 * 8) * 2, BT + (size_t)r * K + c16 * 8);
    }
    CPCOMMIT();

    int nch = N >> 6;
    for (int c = 0; c < nch; c++) {
        int buf = c & 1;
        if (c + 1 < nch) {
            const __nv_bfloat16* Bg = BT + (size_t)(c + 1) * 64 * K;
            uint32_t dst = sB + (buf ^ 1) * 25600;
            #pragma unroll
            for (int i = 0; i < 6; i++) {
                int e = tid + 256 * i;
                int r = e / 24, c16 = e % 24;
                CP16(dst + (r * 200 + c16 * 8) * 2, Bg + (size_t)r * K + c16 * 8);
            }
            CPCOMMIT();
            CPWAIT1();
        } else {
            CPWAIT0();
        }
        __syncthreads();

        float acc[2][4][4];
        #pragma unroll
        for (int i = 0; i < 2; i++)
            #pragma unroll
            for (int j = 0; j < 4; j++)
                #pragma unroll
                for (int k = 0; k < 4; k++) acc[i][j][k] = 0.f;

        uint32_t sBc = sB + buf * 25600;
        #pragma unroll
        for (int ks = 0; ks < 12; ks++) {
            uint32_t a[2][4], b[4][2];
            #pragma unroll
            for (int mt = 0; mt < 2; mt++) {
                uint32_t addr = sA + ((wm * 32 + mt * 16 + (lane & 15)) * 200
                                      + ks * 16 + (lane >> 4) * 8) * 2;
                ldsm_x4(a[mt], addr);
            }
            #pragma unroll
            for (int ntp = 0; ntp < 2; ntp++) {
                uint32_t t4[4];
                ldsm_x4(t4, sBc + ((wnw * 32 + ntp * 16 + (lane & 7) + ((lane >> 4) & 1) * 8) * 200
                                   + ks * 16 + ((lane >> 3) & 1) * 8) * 2);
                b[2 * ntp][0] = t4[0]; b[2 * ntp][1] = t4[1];
                b[2 * ntp + 1][0] = t4[2]; b[2 * ntp + 1][1] = t4[3];
            }
            #pragma unroll
            for (int mt = 0; mt < 2; mt++)
                #pragma unroll
                for (int nt = 0; nt < 4; nt++)
                    mma16816(acc[mt][nt], a[mt], b[nt]);
        }
        __syncthreads();

        int n0 = c * 64;
        #pragma unroll
        for (int mt = 0; mt < 2; mt++) {
            #pragma unroll
            for (int half = 0; half < 2; half++) {
                int m = m0 + wm * 32 + mt * 16 + (lane >> 2) + half * 8;
                #pragma unroll
                for (int nt = 0; nt < 4; nt++) {
                    int col = n0 + wnw * 32 + nt * 8 + (lane & 3) * 2;
                    float v0 = acc[mt][nt][half * 2 + 0] + bias[col];
                    float v1 = acc[mt][nt][half * 2 + 1] + bias[col + 1];
                    if (MODE == 2) {
                        v0 = 0.5f * v0 * (1.f + erff(v0 * 0.70710678118654752f));
                        v1 = 0.5f * v1 * (1.f + erff(v1 * 0.70710678118654752f));
                    }
                    *(__nv_bfloat162*)(outp + (size_t)m * ostride + col) =
                        __floats2bfloat162_rn(v0, v1);
                }
            }
        }
    }
}

// ---------------- mlp2 GEMM: block 128(M) x 192(N, full), K=768 in 64-chunks ----------------
#define MLP2_SMEM (2*128*72*2 + 2*192*72*2)   // 92160
__global__ __launch_bounds__(256)
void gemm_mlp2(const __nv_bfloat16* __restrict__ A,
               const __nv_bfloat16* __restrict__ BT,
               const float* __restrict__ bias,
               const float* __restrict__ res,
               float* __restrict__ outp) {
    extern __shared__ char gsm[];
    uint32_t sA = smem_u32(gsm);          // [2][128][72]
    uint32_t sB = sA + 36864;             // [2][192][72]

    int tid  = threadIdx.x;
    int lane = tid & 31;
    int wid  = tid >> 5;
    int wm   = wid & 1;
    int wnw  = wid >> 1;
    int m0 = blockIdx.x * 128;
    const int K = 768;
    const int nch = 12;

    #pragma unroll
    for (int i = 0; i < 4; i++) {
        int e = tid + 256 * i; int r = e >> 3, c16 = e & 7;
        CP16(sA + (r * 72 + c16 * 8) * 2, A + (size_t)(m0 + r) * K + c16 * 8);
    }
    #pragma unroll
    for (int i = 0; i < 6; i++) {
        int e = tid + 256 * i; int r = e >> 3, c16 = e & 7;
        CP16(sB + (r * 72 + c16 * 8) * 2, BT + (size_t)r * K + c16 * 8);
    }
    CPCOMMIT();

    float acc[4][6][4];
    #pragma unroll
    for (int i = 0; i < 4; i++)
        #pragma unroll
        for (int j = 0; j < 6; j++)
            #pragma unroll
            for (int k = 0; k < 4; k++) acc[i][j][k] = 0.f;

    for (int c = 0; c < nch; c++) {
        int buf = c & 1;
        if (c + 1 < nch) {
            int kc = (c + 1) * 64;
            uint32_t dA = sA + (buf ^ 1) * 18432;
            uint32_t dB = sB + (buf ^ 1) * 27648;
            #pragma unroll
            for (int i = 0; i < 4; i++) {
                int e = tid + 256 * i; int r = e >> 3, c16 = e & 7;
                CP16(dA + (r * 72 + c16 * 8) * 2, A + (size_t)(m0 + r) * K + kc + c16 * 8);
            }
            #pragma unroll
            for (int i = 0; i < 6; i++) {
                int e = tid + 256 * i; int r = e >> 3, c16 = e & 7;
                CP16(dB + (r * 72 + c16 * 8) * 2, BT + (size_t)r * K + kc + c16 * 8);
            }
            CPCOMMIT();
            CPWAIT1();
        } else {
            CPWAIT0();
        }
        __syncthreads();

        uint32_t sAc = sA + buf * 18432;
        uint32_t sBc = sB + buf * 27648;
        #pragma unroll
        for (int ks = 0; ks < 4; ks++) {
            uint32_t a[4][4], b[6][2];
            #pragma unroll
            for (int mt = 0; mt < 4; mt++) {
                uint32_t addr = sAc + ((wm * 64 + mt * 16 + (lane & 15)) * 72
                                       + ks * 16 + (lane >> 4) * 8) * 2;
                ldsm_x4(a[mt], addr);
            }
            #pragma unroll
            for (int ntp = 0; ntp < 3; ntp++) {
                uint32_t t4[4];
                ldsm_x4(t4, sBc + ((wnw * 48 + ntp * 16 + (lane & 7) + ((lane >> 4) & 1) * 8) * 72
                                   + ks * 16 + ((lane >> 3) & 1) * 8) * 2);
                b[2 * ntp][0] = t4[0]; b[2 * ntp][1] = t4[1];
                b[2 * ntp + 1][0] = t4[2]; b[2 * ntp + 1][1] = t4[3];
            }
            #pragma unroll
            for (int mt = 0; mt < 4; mt++)
                #pragma unroll
                for (int nt = 0; nt < 6; nt++)
                    mma16816(acc[mt][nt], a[mt], b[nt]);
        }
        __syncthreads();
    }

    #pragma unroll
    for (int mt = 0; mt < 4; mt++) {
        #pragma unroll
        for (int half = 0; half < 2; half++) {
            int m = m0 + wm * 64 + mt * 16 + (lane >> 2) + half * 8;
            #pragma unroll
            for (int nt = 0; nt < 6; nt++) {
                int col = wnw * 48 + nt * 8 + (lane & 3) * 2;
                size_t i0 = (size_t)m * 192 + col;
                outp[i0]     = res[i0]     + acc[mt][nt][half * 2 + 0] + bias[col];
                outp[i0 + 1] = res[i0 + 1] + acc[mt][nt][half * 2 + 1] + bias[col + 1];
            }
        }
    }
}

// ---------------- proj GEMM (128x192) + un-window + residual + LN2, 512 threads ----------------
#define PROJ_SMEM (20480 + 76800 + 8192)   // 105472
__global__ __launch_bounds__(512)
void gemm_proj_ln(const __nv_bfloat16* __restrict__ A,
                  const __nv_bfloat16* __restrict__ BT,
                  const float* __restrict__ bias,
                  const float* __restrict__ res,
                  float* __restrict__ x1out,
                  const float* __restrict__ g2,
                  const float* __restrict__ b2,
                  __nv_bfloat16* __restrict__ h2out) {
    extern __shared__ char psm[];
    uint32_t sAbase = smem_u32(psm);              // [2][128][40] bf16
    uint32_t sBbase = sAbase + 20480;             // [192][200]   bf16
    float* part = (float*)(psm + 97280);          // [8][128][2]

    int tid  = threadIdx.x;
    int lane = tid & 31;
    int wid  = tid >> 5;
    int wm   = wid & 1;
    int wnw  = wid >> 1;
    int m0 = blockIdx.x * 128;
    const int K = 192;
    const int nch = 6;

    for (int i = tid; i < 192 * 24; i += 512) {
        int r = i / 24, c16 = i % 24;
        CP16(sBbase + (r * 200 + c16 * 8) * 2, BT + (size_t)r * 192 + c16 * 8);
    }
    {
        int r = tid >> 2, cs = (tid & 3) * 8;
        CP16(sAbase + (r * 40 + cs) * 2, A + (size_t)(m0 + r) * K + cs);
    }
    CPCOMMIT();

    float acc[4][3][4];
    #pragma unroll
    for (int i = 0; i < 4; i++)
        #pragma unroll
        for (int j = 0; j < 3; j++)
            #pragma unroll
            for (int k = 0; k < 4; k++) acc[i][j][k] = 0.f;

    for (int c = 0; c < nch; c++) {
        int buf = c & 1;
        if (c + 1 < nch) {
            int kc = (c + 1) * 32;
            int r = tid >> 2, cs = (tid & 3) * 8;
            CP16(sAbase + (buf ^ 1) * 10240 + (r * 40 + cs) * 2,
                 A + (size_t)(m0 + r) * K + kc + cs);
            CPCOMMIT();
            CPWAIT1();
        } else {
            CPWAIT0();
        }
        __syncthreads();

        uint32_t sA = sAbase + buf * 10240;
        #pragma unroll
        for (int ks = 0; ks < 2; ks++) {
            uint32_t a[4][4], b[3][2];
            #pragma unroll
            for (int mt = 0; mt < 4; mt++) {
                uint32_t addr = sA + ((wm * 64 + mt * 16 + (lane & 15)) * 40
                                      + ks * 16 + (lane >> 4) * 8) * 2;
                ldsm_x4(a[mt], addr);
            }
            {
                uint32_t t4[4];
                ldsm_x4(t4, sBbase + ((wnw * 24 + (lane & 7) + ((lane >> 4) & 1) * 8) * 200
                                      + c * 32 + ks * 16 + ((lane >> 3) & 1) * 8) * 2);
                b[0][0] = t4[0]; b[0][1] = t4[1];
                b[1][0] = t4[2]; b[1][1] = t4[3];
                int L = lane & 15;
                ldsm_x2(b[2], sBbase + ((wnw * 24 + 16 + (L & 7)) * 200
                                        + c * 32 + ks * 16 + (L >> 3) * 8) * 2);
            }
            #pragma unroll
            for (int mt = 0; mt < 4; mt++)
                #pragma unroll
                for (int nt = 0; nt < 3; nt++)
                    mma16816(acc[mt][nt], a[mt], b[nt]);
        }
        __syncthreads();
    }

    #pragma unroll
    for (int mt = 0; mt < 4; mt++) {
        #pragma unroll
        for (int half = 0; half < 2; half++) {
            int row = wm * 64 + mt * 16 + (lane >> 2) + half * 8;
            int m = m0 + row;
            int b_ = m >> 12, rem = m & 4095, wnn = rem >> 6, t = rem & 63;
            int y  = (((wnn >> 3) << 3) + (t >> 3) + SH) & 63;
            int xx = (((wnn & 7)  << 3) + (t & 7)  + SH) & 63;
            size_t pixbase = (size_t)(((b_ << 6) + y) * 64 + xx) * CC;
            float s = 0.f, s2 = 0.f;
            #pragma unroll
            for (int nt = 0; nt < 3; nt++) {
                #pragma unroll
                for (int e = 0; e < 2; e++) {
                    int col = wnw * 24 + nt * 8 + (lane & 3) * 2 + e;
                    float v = acc[mt][nt][half * 2 + e] + bias[col] + res[pixbase + col];
                    acc[mt][nt][half * 2 + e] = v;
                    x1out[pixbase + col] = v;
                    s += v; s2 += v * v;
                }
            }
            s  += __shfl_xor_sync(0xffffffffu, s, 1);
            s  += __shfl_xor_sync(0xffffffffu, s, 2);
            s2 += __shfl_xor_sync(0xffffffffu, s2, 1);
            s2 += __shfl_xor_sync(0xffffffffu, s2, 2);
            if ((lane & 3) == 0) {
                part[(wnw * 128 + row) * 2]     = s;
                part[(wnw * 128 + row) * 2 + 1] = s2;
            }
        }
    }
    __syncthreads();

    #pragma unroll
    for (int mt = 0; mt < 4; mt++) {
        #pragma unroll
        for (int half = 0; half < 2; half++) {
            int row = wm * 64 + mt * 16 + (lane >> 2) + half * 8;
            int m = m0 + row;
            int b_ = m >> 12, rem = m & 4095, wnn = rem >> 6, t = rem & 63;
            int y  = (((wnn >> 3) << 3) + (t >> 3) + SH) & 63;
            int xx = (((wnn & 7)  << 3) + (t & 7)  + SH) & 63;
            size_t pixbase = (size_t)(((b_ << 6) + y) * 64 + xx) * CC;
            float S = 0.f, S2 = 0.f;
            #pragma unroll
            for (int w = 0; w < 8; w++) {
                S  += part[(w * 128 + row) * 2];
                S2 += part[(w * 128 + row) * 2 + 1];
            }
            float mu  = S * (1.f / CC);
            float var = S2 * (1.f / CC) - mu * mu;
            float inv = rsqrtf(var + 1e-5f);
            #pragma unroll
            for (int nt = 0; nt < 3; nt++) {
                int col = wnw * 24 + nt * 8 + (lane & 3) * 2;
                float h0 = (acc[mt][nt][half * 2 + 0] - mu) * inv * g2[col]     + b2[col];
                float h1 = (acc[mt][nt][half * 2 + 1] - mu) * inv * g2[col + 1] + b2[col + 1];
                *(__nv_bfloat162*)(h2out + pixbase + col) = __floats2bfloat162_rn(h0, h1);
            }
        }
    }
}

// ---------------- launch ----------------
extern "C" void kernel_launch(void* const* d_in, const int* in_sizes, int n_in,
                              void* d_out, int out_size) {
    const float* x       = (const float*)d_in[0];
    const float* g1      = (const float*)d_in[1];
    const float* b1      = (const float*)d_in[2];
    const float* w_qkv   = (const float*)d_in[3];
    const float* b_qkv   = (const float*)d_in[4];
    const float* rel_pos = (const float*)d_in[5];
    const float* w_proj  = (const float*)d_in[6];
    const float* b_proj  = (const float*)d_in[7];
    const float* g2      = (const float*)d_in[8];
    const float* b2      = (const float*)d_in[9];
    const float* w_mlp1  = (const float*)d_in[10];
    const float* b_mlp1  = (const float*)d_in[11];
    const float* w_mlp2  = (const float*)d_in[12];
    const float* b_mlp2  = (const float*)d_in[13];
    float* out = (float*)d_out;

    __nv_bfloat16 *p_hwin, *p_qkv, *p_attn, *p_h2, *p_hid;
    __nv_bfloat16 *p_wqkvT, *p_wprojT, *p_wmlp1T, *p_wmlp2T;
    float *p_x1;
    cudaGetSymbolAddress((void**)&p_hwin,   g_hwin_bf);
    cudaGetSymbolAddress((void**)&p_qkv,    g_qkv_bf);
    cudaGetSymbolAddress((void**)&p_attn,   g_attn_bf);
    cudaGetSymbolAddress((void**)&p_x1,     g_x1);
    cudaGetSymbolAddress((void**)&p_h2,     g_h2_bf);
    cudaGetSymbolAddress((void**)&p_hid,    g_hid_bf);
    cudaGetSymbolAddress((void**)&p_wqkvT,  g_wqkvT);
    cudaGetSymbolAddress((void**)&p_wprojT, g_wprojT);
    cudaGetSymbolAddress((void**)&p_wmlp1T, g_wmlp1T);
    cudaGetSymbolAddress((void**)&p_wmlp2T, g_wmlp2T);

    cudaFuncSetAttribute(gemm_ares<0>, cudaFuncAttributeMaxDynamicSharedMemorySize, ARES_SMEM);
    cudaFuncSetAttribute(gemm_ares<2>, cudaFuncAttributeMaxDynamicSharedMemorySize, ARES_SMEM);
    cudaFuncSetAttribute(gemm_mlp2,   cudaFuncAttributeMaxDynamicSharedMemorySize, MLP2_SMEM);
    cudaFuncSetAttribute(gemm_proj_ln, cudaFuncAttributeMaxDynamicSharedMemorySize, PROJ_SMEM);
    cudaFuncSetAttribute(attn_mma_kernel, cudaFuncAttributeMaxDynamicSharedMemorySize, AT_SMEM);

    // weight transpose + convert (coalesced tiled, single launch)
    wconv_all<<<432, 256>>>(w_qkv, p_wqkvT, w_proj, p_wprojT,
                            w_mlp1, p_wmlp1T, w_mlp2, p_wmlp2T);

    // 1. LN1 + roll + window partition (bf16, half-warp/token float4)
    ln1_window_kernel<<<TOK / 16, 256>>>(x, g1, b1);

    // 2. qkv: [65536,192] @ [192,576] -> bf16 (A-resident)
    gemm_ares<0><<<TOK / 128, 256, ARES_SMEM>>>(p_hwin, p_wqkvT, b_qkv, p_qkv, 576);

    // 3. windowed attention (HMMA, 128-thread blocks, 2 heads each, 5 blocks/SM)
    attn_mma_kernel<<<dim3(BB * NW, 3), 128, AT_SMEM>>>(rel_pos);

    // 4. proj + un-window + residual + LN2 (512 threads) -> g_x1 (fp32), g_h2 (bf16)
    gemm_proj_ln<<<TOK / 128, 512, PROJ_SMEM>>>(p_attn, p_wprojT, b_proj, x, p_x1, g2, b2, p_h2);

    // 5. mlp1 + gelu: [65536,192] @ [192,768] -> bf16 (A-resident)
    gemm_ares<2><<<TOK / 128, 256, ARES_SMEM>>>(p_h2, p_wmlp1T, b_mlp1, p_hid, 768);

    // 6. mlp2 + residual: [65536,768] @ [768,192] -> fp32 out (full-width N)
    gemm_mlp2<<<TOK / 128, 256, MLP2_SMEM>>>(p_hid, p_wmlp2T, b_mlp2, p_x1, out);
}

// round 16
// speedup vs baseline: 1.0751x; 1.0107x over previous
#include <cuda_runtime.h>
#include <cuda_bf16.h>
#include <math.h>
#include <stdint.h>

// ---------------- problem constants ----------------
#define BB 16
#define HH 64
#define WW 64
#define CC 192
#define HD 32
#define NH 6
#define SH 4
#define NW 64
#define TOK (BB*HH*WW)        // 65536
#define PPW 64

// ---------------- scratch (device globals) ----------------
__device__ __nv_bfloat16 g_hwin_bf[TOK * CC];
__device__ __nv_bfloat16 g_qkv_bf [TOK * 3 * CC];
__device__ __nv_bfloat16 g_attn_bf[TOK * CC];
__device__ float         g_x1     [TOK * CC];
__device__ __nv_bfloat16 g_h2_bf  [TOK * CC];
__device__ __nv_bfloat16 g_hid_bf [TOK * 4 * CC];
__device__ __nv_bfloat16 g_wqkvT [576 * 192];
__device__ __nv_bfloat16 g_wprojT[192 * 192];
__device__ __nv_bfloat16 g_wmlp1T[768 * 192];
__device__ __nv_bfloat16 g_wmlp2T[192 * 768];

// ---------------- PTX helpers ----------------
__device__ __forceinline__ uint32_t smem_u32(const void* p) {
    uint32_t a;
    asm("{ .reg .u64 t; cvta.to.shared.u64 t, %1; cvt.u32.u64 %0, t; }" : "=r"(a) : "l"(p));
    return a;
}
__device__ __forceinline__ void ldsm_x4(uint32_t* r, uint32_t addr) {
    asm volatile("ldmatrix.sync.aligned.m8n8.x4.shared.b16 {%0,%1,%2,%3}, [%4];"
        : "=r"(r[0]), "=r"(r[1]), "=r"(r[2]), "=r"(r[3]) : "r"(addr));
}
__device__ __forceinline__ void ldsm_x2(uint32_t* r, uint32_t addr) {
    asm volatile("ldmatrix.sync.aligned.m8n8.x2.shared.b16 {%0,%1}, [%2];"
        : "=r"(r[0]), "=r"(r[1]) : "r"(addr));
}
__device__ __forceinline__ void ldsm_x4t(uint32_t* r, uint32_t addr) {
    asm volatile("ldmatrix.sync.aligned.m8n8.x4.trans.shared.b16 {%0,%1,%2,%3}, [%4];"
        : "=r"(r[0]), "=r"(r[1]), "=r"(r[2]), "=r"(r[3]) : "r"(addr));
}
__device__ __forceinline__ void mma16816(float* c, const uint32_t* a, const uint32_t* b) {
    asm volatile(
        "mma.sync.aligned.m16n8k16.row.col.f32.bf16.bf16.f32 "
        "{%0,%1,%2,%3}, {%4,%5,%6,%7}, {%8,%9}, {%0,%1,%2,%3};"
        : "+f"(c[0]), "+f"(c[1]), "+f"(c[2]), "+f"(c[3])
        : "r"(a[0]), "r"(a[1]), "r"(a[2]), "r"(a[3]), "r"(b[0]), "r"(b[1]));
}
__device__ __forceinline__ uint32_t packbf(float a, float b) {
    __nv_bfloat162 t = __floats2bfloat162_rn(a, b);
    return *(uint32_t*)&t;
}
#define CP16(dst, src) \
    asm volatile("cp.async.cg.shared.global [%0], [%1], 16;" :: "r"(dst), "l"(src))
#define CPCOMMIT() asm volatile("cp.async.commit_group;" ::)
#define CPWAIT1()  asm volatile("cp.async.wait_group 1;" ::)
#define CPWAIT0()  asm volatile("cp.async.wait_group 0;" ::)

// ---------------- FUSED prep: [0,432) weight transpose tiles; [432,4528) LN1 tokens ----------------
__global__ __launch_bounds__(256)
void prep_kernel(const float* __restrict__ w0, __nv_bfloat16* __restrict__ t0,
                 const float* __restrict__ w1, __nv_bfloat16* __restrict__ t1,
                 const float* __restrict__ w2, __nv_bfloat16* __restrict__ t2,
                 const float* __restrict__ w3, __nv_bfloat16* __restrict__ t3,
                 const float* __restrict__ x,
                 const float* __restrict__ g,
                 const float* __restrict__ b) {
    __shared__ float tile[32][33];
    int bid = blockIdx.x;
    if (bid < 432) {
        // ---- coalesced 32x32 tiled transpose + bf16 convert ----
        const float* w; __nv_bfloat16* t; int K, N, base;
        if      (bid < 108) { w = w0; t = t0; K = 192; N = 576; base = bid; }
        else if (bid < 144) { w = w1; t = t1; K = 192; N = 192; base = bid - 108; }
        else if (bid < 288) { w = w2; t = t2; K = 192; N = 768; base = bid - 144; }
        else                { w = w3; t = t3; K = 768; N = 192; base = bid - 288; }
        int ntiles_n = N >> 5;
        int tk = (base / ntiles_n) << 5;
        int tn = (base % ntiles_n) << 5;
        int tx = threadIdx.x & 31, ty = threadIdx.x >> 5;
        #pragma unroll
        for (int r = 0; r < 4; r++) {
            int k = tk + ty + r * 8;
            tile[ty + r * 8][tx] = w[(size_t)k * N + tn + tx];
        }
        __syncthreads();
        #pragma unroll
        for (int r = 0; r < 4; r++) {
            int n = tn + ty + r * 8;
            t[(size_t)n * K + tk + tx] = __float2bfloat16(tile[tx][ty + r * 8]);
        }
        return;
    }
    // ---- LN1 + roll(-4,-4) + window partition (half-warp/token, float4) ----
    int tid = threadIdx.x;
    int token = (bid - 432) * 16 + (tid >> 4);
    int l = tid & 15;
    int b_  = token >> 12;
    int rem = token & 4095;
    int wn  = rem >> 6;
    int tt  = rem & 63;
    int y  = (((wn >> 3) << 3) + (tt >> 3) + SH) & (HH - 1);
    int xx = (((wn & 7)  << 3) + (tt & 7)  + SH) & (WW - 1);
    const float4* src = (const float4*)(x + (((size_t)b_ * HH + y) * WW + xx) * CC);

    float4 v[3];
    float s = 0.f;
    #pragma unroll
    for (int i = 0; i < 3; i++) {
        v[i] = src[l + 16 * i];
        s += v[i].x + v[i].y + v[i].z + v[i].w;
    }
    #pragma unroll
    for (int o = 8; o; o >>= 1) s += __shfl_xor_sync(0xffffffffu, s, o);
    float mu = s * (1.f / CC);
    float s2 = 0.f;
    #pragma unroll
    for (int i = 0; i < 3; i++) {
        float d0 = v[i].x - mu, d1 = v[i].y - mu, d2 = v[i].z - mu, d3 = v[i].w - mu;
        s2 += d0 * d0 + d1 * d1 + d2 * d2 + d3 * d3;
    }
    #pragma unroll
    for (int o = 8; o; o >>= 1) s2 += __shfl_xor_sync(0xffffffffu, s2, o);
    float inv = rsqrtf(s2 * (1.f / CC) + 1e-5f);

    uint2* dst = (uint2*)(g_hwin_bf + (size_t)token * CC);
    const float4* gp = (const float4*)g;
    const float4* bp = (const float4*)b;
    #pragma unroll
    for (int i = 0; i < 3; i++) {
        float4 gg = gp[l + 16 * i];
        float4 bb = bp[l + 16 * i];
        float h0 = (v[i].x - mu) * inv * gg.x + bb.x;
        float h1 = (v[i].y - mu) * inv * gg.y + bb.y;
        float h2 = (v[i].z - mu) * inv * gg.z + bb.z;
        float h3 = (v[i].w - mu) * inv * gg.w + bb.w;
        uint2 o2;
        o2.x = packbf(h0, h1);
        o2.y = packbf(h2, h3);
        dst[l + 16 * i] = o2;
    }
}

// ---------------- HMMA attention: 1 block = (window, 2 heads), 4 warps ----------------
#define AT_SMEM (30720 + 1808)
__global__ __launch_bounds__(128)
void attn_mma_kernel(const float* __restrict__ rel_pos) {
    extern __shared__ char sm[];
    __nv_bfloat16* base = (__nv_bfloat16*)sm;   // 6 x [64][40]: q0,q1,k0,k1,v0,v1
    float*         rs   = (float*)(sm + 30720); // [2][225]

    int tid = threadIdx.x;
    int win = blockIdx.x;
    int h0  = blockIdx.y * 2;
    int wn  = win & 63;
    int tokbase = win * 64;
    bool lastRow = (wn >> 3) == 7;
    bool lastCol = (wn & 7) == 7;

    {
        const uint4* src = (const uint4*)(g_qkv_bf + (size_t)tokbase * 576);
        #pragma unroll
        for (int i = 0; i < 12; i++) {
            int e = tid + 128 * i;           // 0..1535
            int mat = e >> 9;                // 0=q 1=k 2=v
            int rem = e & 511;
            int r = rem >> 3;
            int lh = (rem >> 2) & 1;
            int c4 = rem & 3;
            uint4 v = src[r * 72 + mat * 24 + (h0 + lh) * 4 + c4];
            *(uint4*)(base + (mat * 2 + lh) * 2560 + r * 40 + c4 * 8) = v;
        }
        for (int i = tid; i < 450; i += 128) rs[i] = rel_pos[h0 * 225 + i];
    }
    __syncthreads();

    int wid = tid >> 5, lane = tid & 31;
    int lh = wid >> 1;
    int mhalf = wid & 1;
    uint32_t qb = smem_u32(base + lh * 2560);
    uint32_t kb = smem_u32(base + (2 + lh) * 2560);
    uint32_t vb = smem_u32(base + (4 + lh) * 2560);

    float sacc[2][8][4];
    #pragma unroll
    for (int mt = 0; mt < 2; mt++)
        #pragma unroll
        for (int nt = 0; nt < 8; nt++)
            #pragma unroll
            for (int e = 0; e < 4; e++) sacc[mt][nt][e] = 0.f;

    #pragma unroll
    for (int ks16 = 0; ks16 < 2; ks16++) {
        uint32_t a[2][4];
        #pragma unroll
        for (int mt = 0; mt < 2; mt++) {
            int row = mhalf * 32 + mt * 16 + (lane & 15);
            ldsm_x4(a[mt], qb + (row * 40 + ks16 * 16 + (lane >> 4) * 8) * 2);
        }
        uint32_t bf[8][2];
        #pragma unroll
        for (int ntp = 0; ntp < 4; ntp++) {
            uint32_t t4[4];
            ldsm_x4(t4, kb + ((ntp * 16 + (lane & 7) + ((lane >> 4) & 1) * 8) * 40
                              + ks16 * 16 + ((lane >> 3) & 1) * 8) * 2);
            bf[2 * ntp][0] = t4[0]; bf[2 * ntp][1] = t4[1];
            bf[2 * ntp + 1][0] = t4[2]; bf[2 * ntp + 1][1] = t4[3];
        }
        #pragma unroll
        for (int mt = 0; mt < 2; mt++)
            #pragma unroll
            for (int nt = 0; nt < 8; nt++)
                mma16816(sacc[mt][nt], a[mt], bf[nt]);
    }

    const float* rph = rs + lh * 225;
    #pragma unroll
    for (int mt = 0; mt < 2; mt++) {
        #pragma unroll
        for (int half = 0; half < 2; half++) {
            int p = mhalf * 32 + mt * 16 + (lane >> 2) + half * 8;
            int pi = p >> 3, pj = p & 7;
            float mx = -INFINITY;
            #pragma unroll
            for (int nt = 0; nt < 8; nt++) {
                #pragma unroll
                for (int e = 0; e < 2; e++) {
                    int qt = nt * 8 + (lane & 3) * 2 + e;
                    int qi = qt >> 3, qj = qt & 7;
                    float s = sacc[mt][nt][half * 2 + e] * 0.17677669529663687f
                            + rph[(pi - qi + 7) * 15 + (pj - qj + 7)];
                    bool msk = (lastRow && ((pi < SH) != (qi < SH))) ||
                               (lastCol && ((pj < SH) != (qj < SH)));
                    s = msk ? -INFINITY : s;
                    sacc[mt][nt][half * 2 + e] = s;
                    mx = fmaxf(mx, s);
                }
            }
            mx = fmaxf(mx, __shfl_xor_sync(0xffffffffu, mx, 1));
            mx = fmaxf(mx, __shfl_xor_sync(0xffffffffu, mx, 2));
            float sum = 0.f;
            #pragma unroll
            for (int nt = 0; nt < 8; nt++) {
                #pragma unroll
                for (int e = 0; e < 2; e++) {
                    float ex = __expf(sacc[mt][nt][half * 2 + e] - mx);
                    sacc[mt][nt][half * 2 + e] = ex;
                    sum += ex;
                }
            }
            sum += __shfl_xor_sync(0xffffffffu, sum, 1);
            sum += __shfl_xor_sync(0xffffffffu, sum, 2);
            float inv = 1.f / sum;
            #pragma unroll
            for (int nt = 0; nt < 8; nt++) {
                #pragma unroll
                for (int e = 0; e < 2; e++)
                    sacc[mt][nt][half * 2 + e] *= inv;
            }
        }
    }

    float o[2][4][4];
    #pragma unroll
    for (int mt = 0; mt < 2; mt++)
        #pragma unroll
        for (int nt = 0; nt < 4; nt++)
            #pragma unroll
            for (int e = 0; e < 4; e++) o[mt][nt][e] = 0.f;

    #pragma unroll
    for (int j = 0; j < 4; j++) {
        uint32_t bf[4][2];
        #pragma unroll
        for (int ntp = 0; ntp < 2; ntp++) {
            uint32_t t4[4];
            ldsm_x4t(t4, vb + ((j * 16 + (lane & 7) + ((lane >> 3) & 1) * 8) * 40
                               + ntp * 16 + ((lane >> 4) & 1) * 8) * 2);
            bf[2 * ntp][0] = t4[0]; bf[2 * ntp][1] = t4[1];
            bf[2 * ntp + 1][0] = t4[2]; bf[2 * ntp + 1][1] = t4[3];
        }
        #pragma unroll
        for (int mt = 0; mt < 2; mt++) {
            uint32_t afr[4];
            afr[0] = packbf(sacc[mt][2 * j    ][0], sacc[mt][2 * j    ][1]);
            afr[1] = packbf(sacc[mt][2 * j    ][2], sacc[mt][2 * j    ][3]);
            afr[2] = packbf(sacc[mt][2 * j + 1][0], sacc[mt][2 * j + 1][1]);
            afr[3] = packbf(sacc[mt][2 * j + 1][2], sacc[mt][2 * j + 1][3]);
            #pragma unroll
            for (int nt = 0; nt < 4; nt++)
                mma16816(o[mt][nt], afr, bf[nt]);
        }
    }

    #pragma unroll
    for (int mt = 0; mt < 2; mt++) {
        int prow = mhalf * 32 + mt * 16 + (lane >> 2);
        #pragma unroll
        for (int nt = 0; nt < 4; nt++) {
            int col = (h0 + lh) * 32 + nt * 8 + (lane & 3) * 2;
            __nv_bfloat16* dst = g_attn_bf + (size_t)(tokbase + prow) * CC + col;
            *(__nv_bfloat162*)dst = __floats2bfloat162_rn(o[mt][nt][0], o[mt][nt][1]);
            __nv_bfloat16* dst2 = dst + 8 * CC;
            *(__nv_bfloat162*)dst2 = __floats2bfloat162_rn(o[mt][nt][2], o[mt][nt][3]);
        }
    }
}

// ---------------- A-resident GEMM (K=192): block 128(M), N streamed in 64-chunks ----------------
#define ARES_SMEM (51200 + 2*25600)     // 102400
template <int MODE>
__global__ __launch_bounds__(256)
void gemm_ares(const __nv_bfloat16* __restrict__ A,
               const __nv_bfloat16* __restrict__ BT,
               const float* __restrict__ bias,
               __nv_bfloat16* __restrict__ outp,
               int N) {
    extern __shared__ char gsm[];
    uint32_t sA = smem_u32(gsm);          // [128][200] bf16
    uint32_t sB = sA + 51200;             // [2][64][200] bf16

    int tid  = threadIdx.x;
    int lane = tid & 31;
    int wid  = tid >> 5;
    int wm   = wid & 3;
    int wnw  = wid >> 2;
    int m0 = blockIdx.x * 128;
    const int K = 192;
    const int ostride = (MODE == 0) ? 576 : 768;

    #pragma unroll
    for (int i = 0; i < 12; i++) {
        int e = tid + 256 * i;
        int r = e / 24, c16 = e % 24;
        CP16(sA + (r * 200 + c16 * 8) * 2, A + (size_t)(m0 + r) * K + c16 * 8);
    }
    #pragma unroll
    for (int i = 0; i < 6; i++) {
        int e = tid + 256 * i;
        int r = e / 24, c16 = e % 24;
        CP16(sB + (r * 200 + c16 * 8) * 2, BT + (size_t)r * K + c16 * 8);
    }
    CPCOMMIT();

    int nch = N >> 6;
    for (int c = 0; c < nch; c++) {
        int buf = c & 1;
        if (c + 1 < nch) {
            const __nv_bfloat16* Bg = BT + (size_t)(c + 1) * 64 * K;
            uint32_t dst = sB + (buf ^ 1) * 25600;
            #pragma unroll
            for (int i = 0; i < 6; i++) {
                int e = tid + 256 * i;
                int r = e / 24, c16 = e % 24;
                CP16(dst + (r * 200 + c16 * 8) * 2, Bg + (size_t)r * K + c16 * 8);
            }
            CPCOMMIT();
            CPWAIT1();
        } else {
            CPWAIT0();
        }
        __syncthreads();

        float acc[2][4][4];
        #pragma unroll
        for (int i = 0; i < 2; i++)
            #pragma unroll
            for (int j = 0; j < 4; j++)
                #pragma unroll
                for (int k = 0; k < 4; k++) acc[i][j][k] = 0.f;

        uint32_t sBc = sB + buf * 25600;
        #pragma unroll
        for (int ks = 0; ks < 12; ks++) {
            uint32_t a[2][4], b[4][2];
            #pragma unroll
            for (int mt = 0; mt < 2; mt++) {
                uint32_t addr = sA + ((wm * 32 + mt * 16 + (lane & 15)) * 200
                                      + ks * 16 + (lane >> 4) * 8) * 2;
                ldsm_x4(a[mt], addr);
            }
            #pragma unroll
            for (int ntp = 0; ntp < 2; ntp++) {
                uint32_t t4[4];
                ldsm_x4(t4, sBc + ((wnw * 32 + ntp * 16 + (lane & 7) + ((lane >> 4) & 1) * 8) * 200
                                   + ks * 16 + ((lane >> 3) & 1) * 8) * 2);
                b[2 * ntp][0] = t4[0]; b[2 * ntp][1] = t4[1];
                b[2 * ntp + 1][0] = t4[2]; b[2 * ntp + 1][1] = t4[3];
            }
            #pragma unroll
            for (int mt = 0; mt < 2; mt++)
                #pragma unroll
                for (int nt = 0; nt < 4; nt++)
                    mma16816(acc[mt][nt], a[mt], b[nt]);
        }
        __syncthreads();

        int n0 = c * 64;
        #pragma unroll
        for (int mt = 0; mt < 2; mt++) {
            #pragma unroll
            for (int half = 0; half < 2; half++) {
                int m = m0 + wm * 32 + mt * 16 + (lane >> 2) + half * 8;
                #pragma unroll
                for (int nt = 0; nt < 4; nt++) {
                    int col = n0 + wnw * 32 + nt * 8 + (lane & 3) * 2;
                    float v0 = acc[mt][nt][half * 2 + 0] + bias[col];
                    float v1 = acc[mt][nt][half * 2 + 1] + bias[col + 1];
                    if (MODE == 2) {
                        v0 = 0.5f * v0 * (1.f + erff(v0 * 0.70710678118654752f));
                        v1 = 0.5f * v1 * (1.f + erff(v1 * 0.70710678118654752f));
                    }
                    *(__nv_bfloat162*)(outp + (size_t)m * ostride + col) =
                        __floats2bfloat162_rn(v0, v1);
                }
            }
        }
    }
}

// ---------------- mlp2 GEMM: block 128(M) x 192(N, full), K=768 in 64-chunks ----------------
#define MLP2_SMEM (2*128*72*2 + 2*192*72*2)   // 92160
__global__ __launch_bounds__(256)
void gemm_mlp2(const __nv_bfloat16* __restrict__ A,
               const __nv_bfloat16* __restrict__ BT,
               const float* __restrict__ bias,
               const float* __restrict__ res,
               float* __restrict__ outp) {
    extern __shared__ char gsm[];
    uint32_t sA = smem_u32(gsm);          // [2][128][72]
    uint32_t sB = sA + 36864;             // [2][192][72]

    int tid  = threadIdx.x;
    int lane = tid & 31;
    int wid  = tid >> 5;
    int wm   = wid & 1;
    int wnw  = wid >> 1;
    int m0 = blockIdx.x * 128;
    const int K = 768;
    const int nch = 12;

    #pragma unroll
    for (int i = 0; i < 4; i++) {
        int e = tid + 256 * i; int r = e >> 3, c16 = e & 7;
        CP16(sA + (r * 72 + c16 * 8) * 2, A + (size_t)(m0 + r) * K + c16 * 8);
    }
    #pragma unroll
    for (int i = 0; i < 6; i++) {
        int e = tid + 256 * i; int r = e >> 3, c16 = e & 7;
        CP16(sB + (r * 72 + c16 * 8) * 2, BT + (size_t)r * K + c16 * 8);
    }
    CPCOMMIT();

    float acc[4][6][4];
    #pragma unroll
    for (int i = 0; i < 4; i++)
        #pragma unroll
        for (int j = 0; j < 6; j++)
            #pragma unroll
            for (int k = 0; k < 4; k++) acc[i][j][k] = 0.f;

    for (int c = 0; c < nch; c++) {
        int buf = c & 1;
        if (c + 1 < nch) {
            int kc = (c + 1) * 64;
            uint32_t dA = sA + (buf ^ 1) * 18432;
            uint32_t dB = sB + (buf ^ 1) * 27648;
            #pragma unroll
            for (int i = 0; i < 4; i++) {
                int e = tid + 256 * i; int r = e >> 3, c16 = e & 7;
                CP16(dA + (r * 72 + c16 * 8) * 2, A + (size_t)(m0 + r) * K + kc + c16 * 8);
            }
            #pragma unroll
            for (int i = 0; i < 6; i++) {
                int e = tid + 256 * i; int r = e >> 3, c16 = e & 7;
                CP16(dB + (r * 72 + c16 * 8) * 2, BT + (size_t)r * K + kc + c16 * 8);
            }
            CPCOMMIT();
            CPWAIT1();
        } else {
            CPWAIT0();
        }
        __syncthreads();

        uint32_t sAc = sA + buf * 18432;
        uint32_t sBc = sB + buf * 27648;
        #pragma unroll
        for (int ks = 0; ks < 4; ks++) {
            uint32_t a[4][4], b[6][2];
            #pragma unroll
            for (int mt = 0; mt < 4; mt++) {
                uint32_t addr = sAc + ((wm * 64 + mt * 16 + (lane & 15)) * 72
                                       + ks * 16 + (lane >> 4) * 8) * 2;
                ldsm_x4(a[mt], addr);
            }
            #pragma unroll
            for (int ntp = 0; ntp < 3; ntp++) {
                uint32_t t4[4];
                ldsm_x4(t4, sBc + ((wnw * 48 + ntp * 16 + (lane & 7) + ((lane >> 4) & 1) * 8) * 72
                                   + ks * 16 + ((lane >> 3) & 1) * 8) * 2);
                b[2 * ntp][0] = t4[0]; b[2 * ntp][1] = t4[1];
                b[2 * ntp + 1][0] = t4[2]; b[2 * ntp + 1][1] = t4[3];
            }
            #pragma unroll
            for (int mt = 0; mt < 4; mt++)
                #pragma unroll
                for (int nt = 0; nt < 6; nt++)
                    mma16816(acc[mt][nt], a[mt], b[nt]);
        }
        __syncthreads();
    }

    #pragma unroll
    for (int mt = 0; mt < 4; mt++) {
        #pragma unroll
        for (int half = 0; half < 2; half++) {
            int m = m0 + wm * 64 + mt * 16 + (lane >> 2) + half * 8;
            #pragma unroll
            for (int nt = 0; nt < 6; nt++) {
                int col = wnw * 48 + nt * 8 + (lane & 3) * 2;
                size_t i0 = (size_t)m * 192 + col;
                outp[i0]     = res[i0]     + acc[mt][nt][half * 2 + 0] + bias[col];
                outp[i0 + 1] = res[i0 + 1] + acc[mt][nt][half * 2 + 1] + bias[col + 1];
            }
        }
    }
}

// ---------------- proj GEMM (128x192) + un-window + residual + LN2, 512 threads ----------------
#define PROJ_SMEM (20480 + 76800 + 8192)   // 105472
__global__ __launch_bounds__(512)
void gemm_proj_ln(const __nv_bfloat16* __restrict__ A,
                  const __nv_bfloat16* __restrict__ BT,
                  const float* __restrict__ bias,
                  const float* __restrict__ res,
                  float* __restrict__ x1out,
                  const float* __restrict__ g2,
                  const float* __restrict__ b2,
                  __nv_bfloat16* __restrict__ h2out) {
    extern __shared__ char psm[];
    uint32_t sAbase = smem_u32(psm);              // [2][128][40] bf16
    uint32_t sBbase = sAbase + 20480;             // [192][200]   bf16
    float* part = (float*)(psm + 97280);          // [8][128][2]

    int tid  = threadIdx.x;
    int lane = tid & 31;
    int wid  = tid >> 5;
    int wm   = wid & 1;
    int wnw  = wid >> 1;
    int m0 = blockIdx.x * 128;
    const int K = 192;
    const int nch = 6;

    for (int i = tid; i < 192 * 24; i += 512) {
        int r = i / 24, c16 = i % 24;
        CP16(sBbase + (r * 200 + c16 * 8) * 2, BT + (size_t)r * 192 + c16 * 8);
    }
    {
        int r = tid >> 2, cs = (tid & 3) * 8;
        CP16(sAbase + (r * 40 + cs) * 2, A + (size_t)(m0 + r) * K + cs);
    }
    CPCOMMIT();

    float acc[4][3][4];
    #pragma unroll
    for (int i = 0; i < 4; i++)
        #pragma unroll
        for (int j = 0; j < 3; j++)
            #pragma unroll
            for (int k = 0; k < 4; k++) acc[i][j][k] = 0.f;

    for (int c = 0; c < nch; c++) {
        int buf = c & 1;
        if (c + 1 < nch) {
            int kc = (c + 1) * 32;
            int r = tid >> 2, cs = (tid & 3) * 8;
            CP16(sAbase + (buf ^ 1) * 10240 + (r * 40 + cs) * 2,
                 A + (size_t)(m0 + r) * K + kc + cs);
            CPCOMMIT();
            CPWAIT1();
        } else {
            CPWAIT0();
        }
        __syncthreads();

        uint32_t sA = sAbase + buf * 10240;
        #pragma unroll
        for (int ks = 0; ks < 2; ks++) {
            uint32_t a[4][4], b[3][2];
            #pragma unroll
            for (int mt = 0; mt < 4; mt++) {
                uint32_t addr = sA + ((wm * 64 + mt * 16 + (lane & 15)) * 40
                                      + ks * 16 + (lane >> 4) * 8) * 2;
                ldsm_x4(a[mt], addr);
            }
            {
                uint32_t t4[4];
                ldsm_x4(t4, sBbase + ((wnw * 24 + (lane & 7) + ((lane >> 4) & 1) * 8) * 200
                                      + c * 32 + ks * 16 + ((lane >> 3) & 1) * 8) * 2);
                b[0][0] = t4[0]; b[0][1] = t4[1];
                b[1][0] = t4[2]; b[1][1] = t4[3];
                int L = lane & 15;
                ldsm_x2(b[2], sBbase + ((wnw * 24 + 16 + (L & 7)) * 200
                                        + c * 32 + ks * 16 + (L >> 3) * 8) * 2);
            }
            #pragma unroll
            for (int mt = 0; mt < 4; mt++)
                #pragma unroll
                for (int nt = 0; nt < 3; nt++)
                    mma16816(acc[mt][nt], a[mt], b[nt]);
        }
        __syncthreads();
    }

    #pragma unroll
    for (int mt = 0; mt < 4; mt++) {
        #pragma unroll
        for (int half = 0; half < 2; half++) {
            int row = wm * 64 + mt * 16 + (lane >> 2) + half * 8;
            int m = m0 + row;
            int b_ = m >> 12, rem = m & 4095, wnn = rem >> 6, t = rem & 63;
            int y  = (((wnn >> 3) << 3) + (t >> 3) + SH) & 63;
            int xx = (((wnn & 7)  << 3) + (t & 7)  + SH) & 63;
            size_t pixbase = (size_t)(((b_ << 6) + y) * 64 + xx) * CC;
            float s = 0.f, s2 = 0.f;
            #pragma unroll
            for (int nt = 0; nt < 3; nt++) {
                #pragma unroll
                for (int e = 0; e < 2; e++) {
                    int col = wnw * 24 + nt * 8 + (lane & 3) * 2 + e;
                    float v = acc[mt][nt][half * 2 + e] + bias[col] + res[pixbase + col];
                    acc[mt][nt][half * 2 + e] = v;
                    x1out[pixbase + col] = v;
                    s += v; s2 += v * v;
                }
            }
            s  += __shfl_xor_sync(0xffffffffu, s, 1);
            s  += __shfl_xor_sync(0xffffffffu, s, 2);
            s2 += __shfl_xor_sync(0xffffffffu, s2, 1);
            s2 += __shfl_xor_sync(0xffffffffu, s2, 2);
            if ((lane & 3) == 0) {
                part[(wnw * 128 + row) * 2]     = s;
                part[(wnw * 128 + row) * 2 + 1] = s2;
            }
        }
    }
    __syncthreads();

    #pragma unroll
    for (int mt = 0; mt < 4; mt++) {
        #pragma unroll
        for (int half = 0; half < 2; half++) {
            int row = wm * 64 + mt * 16 + (lane >> 2) + half * 8;
            int m = m0 + row;
            int b_ = m >> 12, rem = m & 4095, wnn = rem >> 6, t = rem & 63;
            int y  = (((wnn >> 3) << 3) + (t >> 3) + SH) & 63;
            int xx = (((wnn & 7)  << 3) + (t & 7)  + SH) & 63;
            size_t pixbase = (size_t)(((b_ << 6) + y) * 64 + xx) * CC;
            float S = 0.f, S2 = 0.f;
            #pragma unroll
            for (int w = 0; w < 8; w++) {
                S  += part[(w * 128 + row) * 2];
                S2 += part[(w * 128 + row) * 2 + 1];
            }
            float mu  = S * (1.f / CC);
            float var = S2 * (1.f / CC) - mu * mu;
            float inv = rsqrtf(var + 1e-5f);
            #pragma unroll
            for (int nt = 0; nt < 3; nt++) {
                int col = wnw * 24 + nt * 8 + (lane & 3) * 2;
                float h0 = (acc[mt][nt][half * 2 + 0] - mu) * inv * g2[col]     + b2[col];
                float h1 = (acc[mt][nt][half * 2 + 1] - mu) * inv * g2[col + 1] + b2[col + 1];
                *(__nv_bfloat162*)(h2out + pixbase + col) = __floats2bfloat162_rn(h0, h1);
            }
        }
    }
}

// ---------------- launch ----------------
extern "C" void kernel_launch(void* const* d_in, const int* in_sizes, int n_in,
                              void* d_out, int out_size) {
    const float* x       = (const float*)d_in[0];
    const float* g1      = (const float*)d_in[1];
    const float* b1      = (const float*)d_in[2];
    const float* w_qkv   = (const float*)d_in[3];
    const float* b_qkv   = (const float*)d_in[4];
    const float* rel_pos = (const float*)d_in[5];
    const float* w_proj  = (const float*)d_in[6];
    const float* b_proj  = (const float*)d_in[7];
    const float* g2      = (const float*)d_in[8];
    const float* b2      = (const float*)d_in[9];
    const float* w_mlp1  = (const float*)d_in[10];
    const float* b_mlp1  = (const float*)d_in[11];
    const float* w_mlp2  = (const float*)d_in[12];
    const float* b_mlp2  = (const float*)d_in[13];
    float* out = (float*)d_out;

    __nv_bfloat16 *p_hwin, *p_qkv, *p_attn, *p_h2, *p_hid;
    __nv_bfloat16 *p_wqkvT, *p_wprojT, *p_wmlp1T, *p_wmlp2T;
    float *p_x1;
    cudaGetSymbolAddress((void**)&p_hwin,   g_hwin_bf);
    cudaGetSymbolAddress((void**)&p_qkv,    g_qkv_bf);
    cudaGetSymbolAddress((void**)&p_attn,   g_attn_bf);
    cudaGetSymbolAddress((void**)&p_x1,     g_x1);
    cudaGetSymbolAddress((void**)&p_h2,     g_h2_bf);
    cudaGetSymbolAddress((void**)&p_hid,    g_hid_bf);
    cudaGetSymbolAddress((void**)&p_wqkvT,  g_wqkvT);
    cudaGetSymbolAddress((void**)&p_wprojT, g_wprojT);
    cudaGetSymbolAddress((void**)&p_wmlp1T, g_wmlp1T);
    cudaGetSymbolAddress((void**)&p_wmlp2T, g_wmlp2T);

    cudaFuncSetAttribute(gemm_ares<0>, cudaFuncAttributeMaxDynamicSharedMemorySize, ARES_SMEM);
    cudaFuncSetAttribute(gemm_ares<2>, cudaFuncAttributeMaxDynamicSharedMemorySize, ARES_SMEM);
    cudaFuncSetAttribute(gemm_mlp2,   cudaFuncAttributeMaxDynamicSharedMemorySize, MLP2_SMEM);
    cudaFuncSetAttribute(gemm_proj_ln, cudaFuncAttributeMaxDynamicSharedMemorySize, PROJ_SMEM);
    cudaFuncSetAttribute(attn_mma_kernel, cudaFuncAttributeMaxDynamicSharedMemorySize, AT_SMEM);

    // 1. FUSED prep: weight transpose (432 blocks) + LN1/window (4096 blocks)
    prep_kernel<<<432 + TOK / 16, 256>>>(w_qkv, p_wqkvT, w_proj, p_wprojT,
                                         w_mlp1, p_wmlp1T, w_mlp2, p_wmlp2T,
                                         x, g1, b1);

    // 2. qkv: [65536,192] @ [192,576] -> bf16 (A-resident)
    gemm_ares<0><<<TOK / 128, 256, ARES_SMEM>>>(p_hwin, p_wqkvT, b_qkv, p_qkv, 576);

    // 3. windowed attention (HMMA, 128-thread blocks, 2 heads each)
    attn_mma_kernel<<<dim3(BB * NW, 3), 128, AT_SMEM>>>(rel_pos);

    // 4. proj + un-window + residual + LN2 (512 threads) -> g_x1 (fp32), g_h2 (bf16)
    gemm_proj_ln<<<TOK / 128, 512, PROJ_SMEM>>>(p_attn, p_wprojT, b_proj, x, p_x1, g2, b2, p_h2);

    // 5. mlp1 + gelu: [65536,192] @ [192,768] -> bf16 (A-resident)
    gemm_ares<2><<<TOK / 128, 256, ARES_SMEM>>>(p_h2, p_wmlp1T, b_mlp1, p_hid, 768);

    // 6. mlp2 + residual: [65536,768] @ [768,192] -> fp32 out (full-width N)
    gemm_mlp2<<<TOK / 128, 256, MLP2_SMEM>>>(p_hid, p_wmlp2T, b_mlp2, p_x1, out);
}

// round 17
// speedup vs baseline: 1.0784x; 1.0030x over previous
#include <cuda_runtime.h>
#include <cuda_bf16.h>
#include <math.h>
#include <stdint.h>

// ---------------- problem constants ----------------
#define BB 16
#define HH 64
#define WW 64
#define CC 192
#define HD 32
#define NH 6
#define SH 4
#define NW 64
#define TOK (BB*HH*WW)        // 65536
#define PPW 64

// ---------------- scratch (device globals) ----------------
__device__ __nv_bfloat16 g_hwin_bf[TOK * CC];
__device__ __nv_bfloat16 g_qkv_bf [TOK * 3 * CC];
__device__ __nv_bfloat16 g_attn_bf[TOK * CC];
__device__ float         g_x1     [TOK * CC];
__device__ __nv_bfloat16 g_h2_bf  [TOK * CC];
__device__ __nv_bfloat16 g_hid_bf [TOK * 4 * CC];
__device__ __nv_bfloat16 g_wqkvT [576 * 192];
__device__ __nv_bfloat16 g_wprojT[192 * 192];
__device__ __nv_bfloat16 g_wmlp1T[768 * 192];
__device__ __nv_bfloat16 g_wmlp2T[192 * 768];

// ---------------- PTX helpers ----------------
__device__ __forceinline__ uint32_t smem_u32(const void* p) {
    uint32_t a;
    asm("{ .reg .u64 t; cvta.to.shared.u64 t, %1; cvt.u32.u64 %0, t; }" : "=r"(a) : "l"(p));
    return a;
}
__device__ __forceinline__ void ldsm_x4(uint32_t* r, uint32_t addr) {
    asm volatile("ldmatrix.sync.aligned.m8n8.x4.shared.b16 {%0,%1,%2,%3}, [%4];"
        : "=r"(r[0]), "=r"(r[1]), "=r"(r[2]), "=r"(r[3]) : "r"(addr));
}
__device__ __forceinline__ void ldsm_x2(uint32_t* r, uint32_t addr) {
    asm volatile("ldmatrix.sync.aligned.m8n8.x2.shared.b16 {%0,%1}, [%2];"
        : "=r"(r[0]), "=r"(r[1]) : "r"(addr));
}
__device__ __forceinline__ void ldsm_x4t(uint32_t* r, uint32_t addr) {
    asm volatile("ldmatrix.sync.aligned.m8n8.x4.trans.shared.b16 {%0,%1,%2,%3}, [%4];"
        : "=r"(r[0]), "=r"(r[1]), "=r"(r[2]), "=r"(r[3]) : "r"(addr));
}
__device__ __forceinline__ void mma16816(float* c, const uint32_t* a, const uint32_t* b) {
    asm volatile(
        "mma.sync.aligned.m16n8k16.row.col.f32.bf16.bf16.f32 "
        "{%0,%1,%2,%3}, {%4,%5,%6,%7}, {%8,%9}, {%0,%1,%2,%3};"
        : "+f"(c[0]), "+f"(c[1]), "+f"(c[2]), "+f"(c[3])
        : "r"(a[0]), "r"(a[1]), "r"(a[2]), "r"(a[3]), "r"(b[0]), "r"(b[1]));
}
__device__ __forceinline__ uint32_t packbf(float a, float b) {
    __nv_bfloat162 t = __floats2bfloat162_rn(a, b);
    return *(uint32_t*)&t;
}
#define CP16(dst, src) \
    asm volatile("cp.async.cg.shared.global [%0], [%1], 16;" :: "r"(dst), "l"(src))
#define CPCOMMIT() asm volatile("cp.async.commit_group;" ::)
#define CPWAIT1()  asm volatile("cp.async.wait_group 1;" ::)
#define CPWAIT0()  asm volatile("cp.async.wait_group 0;" ::)

// ---------------- FUSED prep: [0,432) weight transpose tiles; [432,4528) LN1 tokens ----------------
__global__ __launch_bounds__(256)
void prep_kernel(const float* __restrict__ w0, __nv_bfloat16* __restrict__ t0,
                 const float* __restrict__ w1, __nv_bfloat16* __restrict__ t1,
                 const float* __restrict__ w2, __nv_bfloat16* __restrict__ t2,
                 const float* __restrict__ w3, __nv_bfloat16* __restrict__ t3,
                 const float* __restrict__ x,
                 const float* __restrict__ g,
                 const float* __restrict__ b) {
    __shared__ float tile[32][33];
    int bid = blockIdx.x;
    if (bid < 432) {
        const float* w; __nv_bfloat16* t; int K, N, base;
        if      (bid < 108) { w = w0; t = t0; K = 192; N = 576; base = bid; }
        else if (bid < 144) { w = w1; t = t1; K = 192; N = 192; base = bid - 108; }
        else if (bid < 288) { w = w2; t = t2; K = 192; N = 768; base = bid - 144; }
        else                { w = w3; t = t3; K = 768; N = 192; base = bid - 288; }
        int ntiles_n = N >> 5;
        int tk = (base / ntiles_n) << 5;
        int tn = (base % ntiles_n) << 5;
        int tx = threadIdx.x & 31, ty = threadIdx.x >> 5;
        #pragma unroll
        for (int r = 0; r < 4; r++) {
            int k = tk + ty + r * 8;
            tile[ty + r * 8][tx] = w[(size_t)k * N + tn + tx];
        }
        __syncthreads();
        #pragma unroll
        for (int r = 0; r < 4; r++) {
            int n = tn + ty + r * 8;
            t[(size_t)n * K + tk + tx] = __float2bfloat16(tile[tx][ty + r * 8]);
        }
        return;
    }
    // ---- LN1 + roll(-4,-4) + window partition (half-warp/token, float4) ----
    int tid = threadIdx.x;
    int token = (bid - 432) * 16 + (tid >> 4);
    int l = tid & 15;
    int b_  = token >> 12;
    int rem = token & 4095;
    int wn  = rem >> 6;
    int tt  = rem & 63;
    int y  = (((wn >> 3) << 3) + (tt >> 3) + SH) & (HH - 1);
    int xx = (((wn & 7)  << 3) + (tt & 7)  + SH) & (WW - 1);
    const float4* src = (const float4*)(x + (((size_t)b_ * HH + y) * WW + xx) * CC);

    float4 v[3];
    float s = 0.f;
    #pragma unroll
    for (int i = 0; i < 3; i++) {
        v[i] = src[l + 16 * i];
        s += v[i].x + v[i].y + v[i].z + v[i].w;
    }
    #pragma unroll
    for (int o = 8; o; o >>= 1) s += __shfl_xor_sync(0xffffffffu, s, o);
    float mu = s * (1.f / CC);
    float s2 = 0.f;
    #pragma unroll
    for (int i = 0; i < 3; i++) {
        float d0 = v[i].x - mu, d1 = v[i].y - mu, d2 = v[i].z - mu, d3 = v[i].w - mu;
        s2 += d0 * d0 + d1 * d1 + d2 * d2 + d3 * d3;
    }
    #pragma unroll
    for (int o = 8; o; o >>= 1) s2 += __shfl_xor_sync(0xffffffffu, s2, o);
    float inv = rsqrtf(s2 * (1.f / CC) + 1e-5f);

    uint2* dst = (uint2*)(g_hwin_bf + (size_t)token * CC);
    const float4* gp = (const float4*)g;
    const float4* bp = (const float4*)b;
    #pragma unroll
    for (int i = 0; i < 3; i++) {
        float4 gg = gp[l + 16 * i];
        float4 bb = bp[l + 16 * i];
        float h0 = (v[i].x - mu) * inv * gg.x + bb.x;
        float h1 = (v[i].y - mu) * inv * gg.y + bb.y;
        float h2 = (v[i].z - mu) * inv * gg.z + bb.z;
        float h3 = (v[i].w - mu) * inv * gg.w + bb.w;
        uint2 o2;
        o2.x = packbf(h0, h1);
        o2.y = packbf(h2, h3);
        dst[l + 16 * i] = o2;
    }
}

// ---------------- HMMA attention: 1 block = (window, 2 heads), 4 warps ----------------
#define AT_SMEM (30720 + 1808)
__global__ __launch_bounds__(128)
void attn_mma_kernel(const float* __restrict__ rel_pos) {
    extern __shared__ char sm[];
    __nv_bfloat16* base = (__nv_bfloat16*)sm;   // 6 x [64][40]: q0,q1,k0,k1,v0,v1
    float*         rs   = (float*)(sm + 30720); // [2][225]

    int tid = threadIdx.x;
    int win = blockIdx.x;
    int h0  = blockIdx.y * 2;
    int wn  = win & 63;
    int tokbase = win * 64;
    bool lastRow = (wn >> 3) == 7;
    bool lastCol = (wn & 7) == 7;

    {
        const uint4* src = (const uint4*)(g_qkv_bf + (size_t)tokbase * 576);
        #pragma unroll
        for (int i = 0; i < 12; i++) {
            int e = tid + 128 * i;           // 0..1535
            int mat = e >> 9;                // 0=q 1=k 2=v
            int rem = e & 511;
            int r = rem >> 3;
            int lh = (rem >> 2) & 1;
            int c4 = rem & 3;
            uint4 v = src[r * 72 + mat * 24 + (h0 + lh) * 4 + c4];
            *(uint4*)(base + (mat * 2 + lh) * 2560 + r * 40 + c4 * 8) = v;
        }
        for (int i = tid; i < 450; i += 128) rs[i] = rel_pos[h0 * 225 + i];
    }
    __syncthreads();

    int wid = tid >> 5, lane = tid & 31;
    int lh = wid >> 1;
    int mhalf = wid & 1;
    uint32_t qb = smem_u32(base + lh * 2560);
    uint32_t kb = smem_u32(base + (2 + lh) * 2560);
    uint32_t vb = smem_u32(base + (4 + lh) * 2560);

    float sacc[2][8][4];
    #pragma unroll
    for (int mt = 0; mt < 2; mt++)
        #pragma unroll
        for (int nt = 0; nt < 8; nt++)
            #pragma unroll
            for (int e = 0; e < 4; e++) sacc[mt][nt][e] = 0.f;

    #pragma unroll
    for (int ks16 = 0; ks16 < 2; ks16++) {
        uint32_t a[2][4];
        #pragma unroll
        for (int mt = 0; mt < 2; mt++) {
            int row = mhalf * 32 + mt * 16 + (lane & 15);
            ldsm_x4(a[mt], qb + (row * 40 + ks16 * 16 + (lane >> 4) * 8) * 2);
        }
        uint32_t bf[8][2];
        #pragma unroll
        for (int ntp = 0; ntp < 4; ntp++) {
            uint32_t t4[4];
            ldsm_x4(t4, kb + ((ntp * 16 + (lane & 7) + ((lane >> 4) & 1) * 8) * 40
                              + ks16 * 16 + ((lane >> 3) & 1) * 8) * 2);
            bf[2 * ntp][0] = t4[0]; bf[2 * ntp][1] = t4[1];
            bf[2 * ntp + 1][0] = t4[2]; bf[2 * ntp + 1][1] = t4[3];
        }
        #pragma unroll
        for (int mt = 0; mt < 2; mt++)
            #pragma unroll
            for (int nt = 0; nt < 8; nt++)
                mma16816(sacc[mt][nt], a[mt], bf[nt]);
    }

    const float* rph = rs + lh * 225;
    #pragma unroll
    for (int mt = 0; mt < 2; mt++) {
        #pragma unroll
        for (int half = 0; half < 2; half++) {
            int p = mhalf * 32 + mt * 16 + (lane >> 2) + half * 8;
            int pi = p >> 3, pj = p & 7;
            float mx = -INFINITY;
            #pragma unroll
            for (int nt = 0; nt < 8; nt++) {
                #pragma unroll
                for (int e = 0; e < 2; e++) {
                    int qt = nt * 8 + (lane & 3) * 2 + e;
                    int qi = qt >> 3, qj = qt & 7;
                    float s = sacc[mt][nt][half * 2 + e] * 0.17677669529663687f
                            + rph[(pi - qi + 7) * 15 + (pj - qj + 7)];
                    bool msk = (lastRow && ((pi < SH) != (qi < SH))) ||
                               (lastCol && ((pj < SH) != (qj < SH)));
                    s = msk ? -INFINITY : s;
                    sacc[mt][nt][half * 2 + e] = s;
                    mx = fmaxf(mx, s);
                }
            }
            mx = fmaxf(mx, __shfl_xor_sync(0xffffffffu, mx, 1));
            mx = fmaxf(mx, __shfl_xor_sync(0xffffffffu, mx, 2));
            float sum = 0.f;
            #pragma unroll
            for (int nt = 0; nt < 8; nt++) {
                #pragma unroll
                for (int e = 0; e < 2; e++) {
                    float ex = __expf(sacc[mt][nt][half * 2 + e] - mx);
                    sacc[mt][nt][half * 2 + e] = ex;
                    sum += ex;
                }
            }
            sum += __shfl_xor_sync(0xffffffffu, sum, 1);
            sum += __shfl_xor_sync(0xffffffffu, sum, 2);
            float inv = 1.f / sum;
            #pragma unroll
            for (int nt = 0; nt < 8; nt++) {
                #pragma unroll
                for (int e = 0; e < 2; e++)
                    sacc[mt][nt][half * 2 + e] *= inv;
            }
        }
    }

    float o[2][4][4];
    #pragma unroll
    for (int mt = 0; mt < 2; mt++)
        #pragma unroll
        for (int nt = 0; nt < 4; nt++)
            #pragma unroll
            for (int e = 0; e < 4; e++) o[mt][nt][e] = 0.f;

    #pragma unroll
    for (int j = 0; j < 4; j++) {
        uint32_t bf[4][2];
        #pragma unroll
        for (int ntp = 0; ntp < 2; ntp++) {
            uint32_t t4[4];
            ldsm_x4t(t4, vb + ((j * 16 + (lane & 7) + ((lane >> 3) & 1) * 8) * 40
                               + ntp * 16 + ((lane >> 4) & 1) * 8) * 2);
            bf[2 * ntp][0] = t4[0]; bf[2 * ntp][1] = t4[1];
            bf[2 * ntp + 1][0] = t4[2]; bf[2 * ntp + 1][1] = t4[3];
        }
        #pragma unroll
        for (int mt = 0; mt < 2; mt++) {
            uint32_t afr[4];
            afr[0] = packbf(sacc[mt][2 * j    ][0], sacc[mt][2 * j    ][1]);
            afr[1] = packbf(sacc[mt][2 * j    ][2], sacc[mt][2 * j    ][3]);
            afr[2] = packbf(sacc[mt][2 * j + 1][0], sacc[mt][2 * j + 1][1]);
            afr[3] = packbf(sacc[mt][2 * j + 1][2], sacc[mt][2 * j + 1][3]);
            #pragma unroll
            for (int nt = 0; nt < 4; nt++)
                mma16816(o[mt][nt], afr, bf[nt]);
        }
    }

    #pragma unroll
    for (int mt = 0; mt < 2; mt++) {
        int prow = mhalf * 32 + mt * 16 + (lane >> 2);
        #pragma unroll
        for (int nt = 0; nt < 4; nt++) {
            int col = (h0 + lh) * 32 + nt * 8 + (lane & 3) * 2;
            __nv_bfloat16* dst = g_attn_bf + (size_t)(tokbase + prow) * CC + col;
            *(__nv_bfloat162*)dst = __floats2bfloat162_rn(o[mt][nt][0], o[mt][nt][1]);
            __nv_bfloat16* dst2 = dst + 8 * CC;
            *(__nv_bfloat162*)dst2 = __floats2bfloat162_rn(o[mt][nt][2], o[mt][nt][3]);
        }
    }
}

// ---------------- A-resident GEMM (K=192): block 128(M), N streamed in 64-chunks ----------------
#define ARES_SMEM (51200 + 2*25600)     // 102400
template <int MODE>
__global__ __launch_bounds__(256)
void gemm_ares(const __nv_bfloat16* __restrict__ A,
               const __nv_bfloat16* __restrict__ BT,
               const float* __restrict__ bias,
               __nv_bfloat16* __restrict__ outp,
               int N) {
    extern __shared__ char gsm[];
    uint32_t sA = smem_u32(gsm);          // [128][200] bf16
    uint32_t sB = sA + 51200;             // [2][64][200] bf16

    int tid  = threadIdx.x;
    int lane = tid & 31;
    int wid  = tid >> 5;
    int wm   = wid & 3;
    int wnw  = wid >> 2;
    int m0 = blockIdx.x * 128;
    const int K = 192;
    const int ostride = (MODE == 0) ? 576 : 768;

    #pragma unroll
    for (int i = 0; i < 12; i++) {
        int e = tid + 256 * i;
        int r = e / 24, c16 = e % 24;
        CP16(sA + (r * 200 + c16 * 8) * 2, A + (size_t)(m0 + r) * K + c16 * 8);
    }
    #pragma unroll
    for (int i = 0; i < 6; i++) {
        int e = tid + 256 * i;
        int r = e / 24, c16 = e % 24;
        CP16(sB + (r * 200 + c16 * 8) * 2, BT + (size_t)r * K + c16 * 8);
    }
    CPCOMMIT();

    int nch = N >> 6;
    for (int c = 0; c < nch; c++) {
        int buf = c & 1;
        if (c + 1 < nch) {
            const __nv_bfloat16* Bg = BT + (size_t)(c + 1) * 64 * K;
            uint32_t dst = sB + (buf ^ 1) * 25600;
            #pragma unroll
            for (int i = 0; i < 6; i++) {
                int e = tid + 256 * i;
                int r = e / 24, c16 = e % 24;
                CP16(dst + (r * 200 + c16 * 8) * 2, Bg + (size_t)r * K + c16 * 8);
            }
            CPCOMMIT();
            CPWAIT1();
        } else {
            CPWAIT0();
        }
        __syncthreads();

        float acc[2][4][4];
        #pragma unroll
        for (int i = 0; i < 2; i++)
            #pragma unroll
            for (int j = 0; j < 4; j++)
                #pragma unroll
                for (int k = 0; k < 4; k++) acc[i][j][k] = 0.f;

        uint32_t sBc = sB + buf * 25600;
        #pragma unroll
        for (int ks = 0; ks < 12; ks++) {
            uint32_t a[2][4], b[4][2];
            #pragma unroll
            for (int mt = 0; mt < 2; mt++) {
                uint32_t addr = sA + ((wm * 32 + mt * 16 + (lane & 15)) * 200
                                      + ks * 16 + (lane >> 4) * 8) * 2;
                ldsm_x4(a[mt], addr);
            }
            #pragma unroll
            for (int ntp = 0; ntp < 2; ntp++) {
                uint32_t t4[4];
                ldsm_x4(t4, sBc + ((wnw * 32 + ntp * 16 + (lane & 7) + ((lane >> 4) & 1) * 8) * 200
                                   + ks * 16 + ((lane >> 3) & 1) * 8) * 2);
                b[2 * ntp][0] = t4[0]; b[2 * ntp][1] = t4[1];
                b[2 * ntp + 1][0] = t4[2]; b[2 * ntp + 1][1] = t4[3];
            }
            #pragma unroll
            for (int mt = 0; mt < 2; mt++)
                #pragma unroll
                for (int nt = 0; nt < 4; nt++)
                    mma16816(acc[mt][nt], a[mt], b[nt]);
        }
        __syncthreads();

        int n0 = c * 64;
        #pragma unroll
        for (int mt = 0; mt < 2; mt++) {
            #pragma unroll
            for (int half = 0; half < 2; half++) {
                int m = m0 + wm * 32 + mt * 16 + (lane >> 2) + half * 8;
                #pragma unroll
                for (int nt = 0; nt < 4; nt++) {
                    int col = n0 + wnw * 32 + nt * 8 + (lane & 3) * 2;
                    float v0 = acc[mt][nt][half * 2 + 0] + bias[col];
                    float v1 = acc[mt][nt][half * 2 + 1] + bias[col + 1];
                    if (MODE == 2) {
                        v0 = 0.5f * v0 * (1.f + erff(v0 * 0.70710678118654752f));
                        v1 = 0.5f * v1 * (1.f + erff(v1 * 0.70710678118654752f));
                    }
                    *(__nv_bfloat162*)(outp + (size_t)m * ostride + col) =
                        __floats2bfloat162_rn(v0, v1);
                }
            }
        }
    }
}

// ---------------- mlp2 GEMM: block 128(M) x 192(N, full), K=768 in 64-chunks ----------------
#define MLP2_SMEM (2*128*72*2 + 2*192*72*2)   // 92160
__global__ __launch_bounds__(256)
void gemm_mlp2(const __nv_bfloat16* __restrict__ A,
               const __nv_bfloat16* __restrict__ BT,
               const float* __restrict__ bias,
               const float* __restrict__ res,
               float* __restrict__ outp) {
    extern __shared__ char gsm[];
    uint32_t sA = smem_u32(gsm);          // [2][128][72]
    uint32_t sB = sA + 36864;             // [2][192][72]

    int tid  = threadIdx.x;
    int lane = tid & 31;
    int wid  = tid >> 5;
    int wm   = wid & 1;
    int wnw  = wid >> 1;
    int m0 = blockIdx.x * 128;
    const int K = 768;
    const int nch = 12;

    #pragma unroll
    for (int i = 0; i < 4; i++) {
        int e = tid + 256 * i; int r = e >> 3, c16 = e & 7;
        CP16(sA + (r * 72 + c16 * 8) * 2, A + (size_t)(m0 + r) * K + c16 * 8);
    }
    #pragma unroll
    for (int i = 0; i < 6; i++) {
        int e = tid + 256 * i; int r = e >> 3, c16 = e & 7;
        CP16(sB + (r * 72 + c16 * 8) * 2, BT + (size_t)r * K + c16 * 8);
    }
    CPCOMMIT();

    float acc[4][6][4];
    #pragma unroll
    for (int i = 0; i < 4; i++)
        #pragma unroll
        for (int j = 0; j < 6; j++)
            #pragma unroll
            for (int k = 0; k < 4; k++) acc[i][j][k] = 0.f;

    for (int c = 0; c < nch; c++) {
        int buf = c & 1;
        if (c + 1 < nch) {
            int kc = (c + 1) * 64;
            uint32_t dA = sA + (buf ^ 1) * 18432;
            uint32_t dB = sB + (buf ^ 1) * 27648;
            #pragma unroll
            for (int i = 0; i < 4; i++) {
                int e = tid + 256 * i; int r = e >> 3, c16 = e & 7;
                CP16(dA + (r * 72 + c16 * 8) * 2, A + (size_t)(m0 + r) * K + kc + c16 * 8);
            }
            #pragma unroll
            for (int i = 0; i < 6; i++) {
                int e = tid + 256 * i; int r = e >> 3, c16 = e & 7;
                CP16(dB + (r * 72 + c16 * 8) * 2, BT + (size_t)r * K + kc + c16 * 8);
            }
            CPCOMMIT();
            CPWAIT1();
        } else {
            CPWAIT0();
        }
        __syncthreads();

        uint32_t sAc = sA + buf * 18432;
        uint32_t sBc = sB + buf * 27648;
        #pragma unroll
        for (int ks = 0; ks < 4; ks++) {
            uint32_t a[4][4], b[6][2];
            #pragma unroll
            for (int mt = 0; mt < 4; mt++) {
                uint32_t addr = sAc + ((wm * 64 + mt * 16 + (lane & 15)) * 72
                                       + ks * 16 + (lane >> 4) * 8) * 2;
                ldsm_x4(a[mt], addr);
            }
            #pragma unroll
            for (int ntp = 0; ntp < 3; ntp++) {
                uint32_t t4[4];
                ldsm_x4(t4, sBc + ((wnw * 48 + ntp * 16 + (lane & 7) + ((lane >> 4) & 1) * 8) * 72
                                   + ks * 16 + ((lane >> 3) & 1) * 8) * 2);
                b[2 * ntp][0] = t4[0]; b[2 * ntp][1] = t4[1];
                b[2 * ntp + 1][0] = t4[2]; b[2 * ntp + 1][1] = t4[3];
            }
            #pragma unroll
            for (int mt = 0; mt < 4; mt++)
                #pragma unroll
                for (int nt = 0; nt < 6; nt++)
                    mma16816(acc[mt][nt], a[mt], b[nt]);
        }
        __syncthreads();
    }

    #pragma unroll
    for (int mt = 0; mt < 4; mt++) {
        #pragma unroll
        for (int half = 0; half < 2; half++) {
            int m = m0 + wm * 64 + mt * 16 + (lane >> 2) + half * 8;
            #pragma unroll
            for (int nt = 0; nt < 6; nt++) {
                int col = wnw * 48 + nt * 8 + (lane & 3) * 2;
                size_t i0 = (size_t)m * 192 + col;
                outp[i0]     = res[i0]     + acc[mt][nt][half * 2 + 0] + bias[col];
                outp[i0 + 1] = res[i0 + 1] + acc[mt][nt][half * 2 + 1] + bias[col + 1];
            }
        }
    }
}

// ---------------- proj GEMM (128x192, A+B both smem-resident) + LN2, 512 threads ----------------
// ONE sync before compute; 12 uninterrupted k-steps.
#define PROJ_SMEM (51200 + 76800 + 8192)   // 136192
__global__ __launch_bounds__(512)
void gemm_proj_ln(const __nv_bfloat16* __restrict__ A,
                  const __nv_bfloat16* __restrict__ BT,
                  const float* __restrict__ bias,
                  const float* __restrict__ res,
                  float* __restrict__ x1out,
                  const float* __restrict__ g2,
                  const float* __restrict__ b2,
                  __nv_bfloat16* __restrict__ h2out) {
    extern __shared__ char psm[];
    uint32_t sA = smem_u32(psm);                  // [128][200] bf16
    uint32_t sB = sA + 51200;                     // [192][200] bf16
    float* part = (float*)(psm + 128000);         // [8][128][2]

    int tid  = threadIdx.x;
    int lane = tid & 31;
    int wid  = tid >> 5;
    int wm   = wid & 1;         // 2 warps along M (64 rows)
    int wnw  = wid >> 1;        // 8 warps along N (24 cols)
    int m0 = blockIdx.x * 128;
    const int K = 192;

    // load ALL of A (128x192) and B (192x192) once
    #pragma unroll
    for (int i = 0; i < 6; i++) {
        int e = tid + 512 * i;           // 0..3071
        int r = e / 24, c16 = e % 24;
        CP16(sA + (r * 200 + c16 * 8) * 2, A + (size_t)(m0 + r) * K + c16 * 8);
    }
    #pragma unroll
    for (int i = 0; i < 9; i++) {
        int e = tid + 512 * i;           // 0..4607
        int r = e / 24, c16 = e % 24;
        CP16(sB + (r * 200 + c16 * 8) * 2, BT + (size_t)r * K + c16 * 8);
    }
    CPCOMMIT();
    CPWAIT0();
    __syncthreads();

    float acc[4][3][4];
    #pragma unroll
    for (int i = 0; i < 4; i++)
        #pragma unroll
        for (int j = 0; j < 3; j++)
            #pragma unroll
            for (int k = 0; k < 4; k++) acc[i][j][k] = 0.f;

    #pragma unroll
    for (int ks = 0; ks < 12; ks++) {
        uint32_t a[4][4], b[3][2];
        #pragma unroll
        for (int mt = 0; mt < 4; mt++) {
            uint32_t addr = sA + ((wm * 64 + mt * 16 + (lane & 15)) * 200
                                  + ks * 16 + (lane >> 4) * 8) * 2;
            ldsm_x4(a[mt], addr);
        }
        {
            uint32_t t4[4];
            ldsm_x4(t4, sB + ((wnw * 24 + (lane & 7) + ((lane >> 4) & 1) * 8) * 200
                              + ks * 16 + ((lane >> 3) & 1) * 8) * 2);
            b[0][0] = t4[0]; b[0][1] = t4[1];
            b[1][0] = t4[2]; b[1][1] = t4[3];
            int L = lane & 15;
            ldsm_x2(b[2], sB + ((wnw * 24 + 16 + (L & 7)) * 200
                                + ks * 16 + (L >> 3) * 8) * 2);
        }
        #pragma unroll
        for (int mt = 0; mt < 4; mt++)
            #pragma unroll
            for (int nt = 0; nt < 3; nt++)
                mma16816(acc[mt][nt], a[mt], b[nt]);
    }
    __syncthreads();

    // pass 1: x1 = res[pix] + acc + bias; write x1; partial row sums (24 cols per warp)
    #pragma unroll
    for (int mt = 0; mt < 4; mt++) {
        #pragma unroll
        for (int half = 0; half < 2; half++) {
            int row = wm * 64 + mt * 16 + (lane >> 2) + half * 8;
            int m = m0 + row;
            int b_ = m >> 12, rem = m & 4095, wnn = rem >> 6, t = rem & 63;
            int y  = (((wnn >> 3) << 3) + (t >> 3) + SH) & 63;
            int xx = (((wnn & 7)  << 3) + (t & 7)  + SH) & 63;
            size_t pixbase = (size_t)(((b_ << 6) + y) * 64 + xx) * CC;
            float s = 0.f, s2 = 0.f;
            #pragma unroll
            for (int nt = 0; nt < 3; nt++) {
                #pragma unroll
                for (int e = 0; e < 2; e++) {
                    int col = wnw * 24 + nt * 8 + (lane & 3) * 2 + e;
                    float v = acc[mt][nt][half * 2 + e] + bias[col] + res[pixbase + col];
                    acc[mt][nt][half * 2 + e] = v;
                    x1out[pixbase + col] = v;
                    s += v; s2 += v * v;
                }
            }
            s  += __shfl_xor_sync(0xffffffffu, s, 1);
            s  += __shfl_xor_sync(0xffffffffu, s, 2);
            s2 += __shfl_xor_sync(0xffffffffu, s2, 1);
            s2 += __shfl_xor_sync(0xffffffffu, s2, 2);
            if ((lane & 3) == 0) {
                part[(wnw * 128 + row) * 2]     = s;
                part[(wnw * 128 + row) * 2 + 1] = s2;
            }
        }
    }
    __syncthreads();

    // pass 2: LN over full 192-col row; write h2 bf16
    #pragma unroll
    for (int mt = 0; mt < 4; mt++) {
        #pragma unroll
        for (int half = 0; half < 2; half++) {
            int row = wm * 64 + mt * 16 + (lane >> 2) + half * 8;
            int m = m0 + row;
            int b_ = m >> 12, rem = m & 4095, wnn = rem >> 6, t = rem & 63;
            int y  = (((wnn >> 3) << 3) + (t >> 3) + SH) & 63;
            int xx = (((wnn & 7)  << 3) + (t & 7)  + SH) & 63;
            size_t pixbase = (size_t)(((b_ << 6) + y) * 64 + xx) * CC;
            float S = 0.f, S2 = 0.f;
            #pragma unroll
            for (int w = 0; w < 8; w++) {
                S  += part[(w * 128 + row) * 2];
                S2 += part[(w * 128 + row) * 2 + 1];
            }
            float mu  = S * (1.f / CC);
            float var = S2 * (1.f / CC) - mu * mu;
            float inv = rsqrtf(var + 1e-5f);
            #pragma unroll
            for (int nt = 0; nt < 3; nt++) {
                int col = wnw * 24 + nt * 8 + (lane & 3) * 2;
                float h0 = (acc[mt][nt][half * 2 + 0] - mu) * inv * g2[col]     + b2[col];
                float h1 = (acc[mt][nt][half * 2 + 1] - mu) * inv * g2[col + 1] + b2[col + 1];
                *(__nv_bfloat162*)(h2out + pixbase + col) = __floats2bfloat162_rn(h0, h1);
            }
        }
    }
}

// ---------------- launch ----------------
extern "C" void kernel_launch(void* const* d_in, const int* in_sizes, int n_in,
                              void* d_out, int out_size) {
    const float* x       = (const float*)d_in[0];
    const float* g1      = (const float*)d_in[1];
    const float* b1      = (const float*)d_in[2];
    const float* w_qkv   = (const float*)d_in[3];
    const float* b_qkv   = (const float*)d_in[4];
    const float* rel_pos = (const float*)d_in[5];
    const float* w_proj  = (const float*)d_in[6];
    const float* b_proj  = (const float*)d_in[7];
    const float* g2      = (const float*)d_in[8];
    const float* b2      = (const float*)d_in[9];
    const float* w_mlp1  = (const float*)d_in[10];
    const float* b_mlp1  = (const float*)d_in[11];
    const float* w_mlp2  = (const float*)d_in[12];
    const float* b_mlp2  = (const float*)d_in[13];
    float* out = (float*)d_out;

    __nv_bfloat16 *p_hwin, *p_qkv, *p_attn, *p_h2, *p_hid;
    __nv_bfloat16 *p_wqkvT, *p_wprojT, *p_wmlp1T, *p_wmlp2T;
    float *p_x1;
    cudaGetSymbolAddress((void**)&p_hwin,   g_hwin_bf);
    cudaGetSymbolAddress((void**)&p_qkv,    g_qkv_bf);
    cudaGetSymbolAddress((void**)&p_attn,   g_attn_bf);
    cudaGetSymbolAddress((void**)&p_x1,     g_x1);
    cudaGetSymbolAddress((void**)&p_h2,     g_h2_bf);
    cudaGetSymbolAddress((void**)&p_hid,    g_hid_bf);
    cudaGetSymbolAddress((void**)&p_wqkvT,  g_wqkvT);
    cudaGetSymbolAddress((void**)&p_wprojT, g_wprojT);
    cudaGetSymbolAddress((void**)&p_wmlp1T, g_wmlp1T);
    cudaGetSymbolAddress((void**)&p_wmlp2T, g_wmlp2T);

    cudaFuncSetAttribute(gemm_ares<0>, cudaFuncAttributeMaxDynamicSharedMemorySize, ARES_SMEM);
    cudaFuncSetAttribute(gemm_ares<2>, cudaFuncAttributeMaxDynamicSharedMemorySize, ARES_SMEM);
    cudaFuncSetAttribute(gemm_mlp2,   cudaFuncAttributeMaxDynamicSharedMemorySize, MLP2_SMEM);
    cudaFuncSetAttribute(gemm_proj_ln, cudaFuncAttributeMaxDynamicSharedMemorySize, PROJ_SMEM);
    cudaFuncSetAttribute(attn_mma_kernel, cudaFuncAttributeMaxDynamicSharedMemorySize, AT_SMEM);

    // 1. FUSED prep: weight transpose (432 blocks) + LN1/window (4096 blocks)
    prep_kernel<<<432 + TOK / 16, 256>>>(w_qkv, p_wqkvT, w_proj, p_wprojT,
                                         w_mlp1, p_wmlp1T, w_mlp2, p_wmlp2T,
                                         x, g1, b1);

    // 2. qkv: [65536,192] @ [192,576] -> bf16 (A-resident)
    gemm_ares<0><<<TOK / 128, 256, ARES_SMEM>>>(p_hwin, p_wqkvT, b_qkv, p_qkv, 576);

    // 3. windowed attention (HMMA, 128-thread blocks, 2 heads each)
    attn_mma_kernel<<<dim3(BB * NW, 3), 128, AT_SMEM>>>(rel_pos);

    // 4. proj + un-window + residual + LN2 (512 threads, fully smem-resident)
    gemm_proj_ln<<<TOK / 128, 512, PROJ_SMEM>>>(p_attn, p_wprojT, b_proj, x, p_x1, g2, b2, p_h2);

    // 5. mlp1 + gelu: [65536,192] @ [192,768] -> bf16 (A-resident)
    gemm_ares<2><<<TOK / 128, 256, ARES_SMEM>>>(p_h2, p_wmlp1T, b_mlp1, p_hid, 768);

    // 6. mlp2 + residual: [65536,768] @ [768,192] -> fp32 out (full-width N)
    gemm_mlp2<<<TOK / 128, 256, MLP2_SMEM>>>(p_hid, p_wmlp2T, b_mlp2, p_x1, out);
}